// round 1
// baseline (speedup 1.0000x reference)
#include <cuda_runtime.h>
#include <cstdint>

#define N_ROWS 8192          // 8*1024
#define D      256
#define K      8192          // codewords used (padding row dropped)
#define DEPTH  4
#define CB_STRIDE ((K + 1) * D)   // 8193*256 per-depth stride in codebooks input

#define BM 128
#define BN 128
#define BK 32
#define CTILES 4             // cand tiles per block -> grid.y = K/(BN*CTILES) = 16

#define LOSS_SCALE (0.25f / (4.0f * 2097152.0f))
#define FLT_BIG 3.402823466e38f

// persistent scratch (no allocations allowed)
__device__ float g_res[N_ROWS * D];
__device__ float g_agg[N_ROWS * D];
__device__ float g_cc[DEPTH * K];
__device__ float g_xx[N_ROWS];
__device__ unsigned long long g_best[N_ROWS];

__device__ __forceinline__ unsigned int f2ord(float f) {
    unsigned int u = __float_as_uint(f);
    return (u & 0x80000000u) ? ~u : (u | 0x80000000u);
}

// reduce two values across a 256-thread block; result valid in thread 0
__device__ __forceinline__ void blockReduce2(float& a, float& b) {
    __shared__ float sa[8], sb[8];
    int lane = threadIdx.x & 31, w = threadIdx.x >> 5;
#pragma unroll
    for (int o = 16; o > 0; o >>= 1) {
        a += __shfl_down_sync(0xffffffffu, a, o);
        b += __shfl_down_sync(0xffffffffu, b, o);
    }
    if (lane == 0) { sa[w] = a; sb[w] = b; }
    __syncthreads();
    if (w == 0) {
        a = (lane < 8) ? sa[lane] : 0.f;
        b = (lane < 8) ? sb[lane] : 0.f;
#pragma unroll
        for (int o = 4; o > 0; o >>= 1) {
            a += __shfl_down_sync(0xffu, a, o);
            b += __shfl_down_sync(0xffu, b, o);
        }
    }
}

// residual = x, agg = 0, best = MAX, loss = 0
__global__ void k_init(const float* __restrict__ x, float* __restrict__ loss) {
    int i = blockIdx.x * blockDim.x + threadIdx.x;
    if (i < N_ROWS * D) { g_res[i] = x[i]; g_agg[i] = 0.f; }
    if (i < N_ROWS) g_best[i] = 0xFFFFFFFFFFFFFFFFULL;
    if (i == 0) *loss = 0.f;
}

// per-row ||x||^2 (initial residual norms)
__global__ void k_xx(const float* __restrict__ x) {
    int row = blockIdx.x;
    float v = x[(size_t)row * D + threadIdx.x];
    float a = v * v, b = 0.f;
    blockReduce2(a, b);
    if (threadIdx.x == 0) g_xx[row] = a;
}

// per-codeword ||c||^2 for all depths
__global__ void k_cc(const float* __restrict__ cbs) {
    int rid = blockIdx.x;               // 0 .. DEPTH*K-1
    int d = rid / K, r = rid % K;
    float v = cbs[(size_t)d * CB_STRIDE + (size_t)r * D + threadIdx.x];
    float a = v * v, b = 0.f;
    blockReduce2(a, b);
    if (threadIdx.x == 0) g_cc[rid] = a;
}

// fused SGEMM + argmin. grid = (N_ROWS/BM, K/(BN*CTILES)), block = 256
__global__ void __launch_bounds__(256, 2)
k_argmin(const float* __restrict__ cb, int d) {
    __shared__ float As[BK][BM + 4];        // pitch 132, k-major transposed
    __shared__ float Bs[BK][BN + 4];
    __shared__ unsigned long long sBest[BM];

    const int tid = threadIdx.x;
    const int tx = tid & 15, ty = tid >> 4;
    const int rowBase = blockIdx.x * BM;
    const int candBase0 = blockIdx.y * (BN * CTILES);
    const float* __restrict__ cc = g_cc + (size_t)d * K;

    float xr[8];
#pragma unroll
    for (int i = 0; i < 8; i++) xr[i] = g_xx[rowBase + ty * 8 + i];

    float bestD[8];
    int bestI[8];
#pragma unroll
    for (int i = 0; i < 8; i++) { bestD[i] = FLT_BIG; bestI[i] = 0; }

    for (int ct = 0; ct < CTILES; ct++) {
        const int candBase = candBase0 + ct * BN;
        float acc[8][8];
#pragma unroll
        for (int i = 0; i < 8; i++)
#pragma unroll
            for (int j = 0; j < 8; j++) acc[i][j] = 0.f;

        for (int kc = 0; kc < D; kc += BK) {
#pragma unroll
            for (int l = 0; l < 4; l++) {
                int s = tid + l * 256;          // 0..1023
                int r = s >> 3;
                int k4 = (s & 7) * 4;
                float4 v = *reinterpret_cast<const float4*>(
                    &g_res[(size_t)(rowBase + r) * D + kc + k4]);
                As[k4 + 0][r] = v.x; As[k4 + 1][r] = v.y;
                As[k4 + 2][r] = v.z; As[k4 + 3][r] = v.w;
            }
#pragma unroll
            for (int l = 0; l < 4; l++) {
                int s = tid + l * 256;
                int r = s >> 3;
                int k4 = (s & 7) * 4;
                float4 v = *reinterpret_cast<const float4*>(
                    &cb[(size_t)(candBase + r) * D + kc + k4]);
                Bs[k4 + 0][r] = v.x; Bs[k4 + 1][r] = v.y;
                Bs[k4 + 2][r] = v.z; Bs[k4 + 3][r] = v.w;
            }
            __syncthreads();
#pragma unroll
            for (int k = 0; k < BK; k++) {
                float4 a0 = *reinterpret_cast<const float4*>(&As[k][ty * 8]);
                float4 a1 = *reinterpret_cast<const float4*>(&As[k][ty * 8 + 4]);
                float4 b0 = *reinterpret_cast<const float4*>(&Bs[k][tx * 8]);
                float4 b1 = *reinterpret_cast<const float4*>(&Bs[k][tx * 8 + 4]);
                float a[8] = {a0.x, a0.y, a0.z, a0.w, a1.x, a1.y, a1.z, a1.w};
                float b[8] = {b0.x, b0.y, b0.z, b0.w, b1.x, b1.y, b1.z, b1.w};
#pragma unroll
                for (int i = 0; i < 8; i++)
#pragma unroll
                    for (int j = 0; j < 8; j++) acc[i][j] += a[i] * b[j];
            }
            __syncthreads();
        }
        // argmin epilogue for this cand tile (ascending cand order -> first-min ties)
#pragma unroll
        for (int i = 0; i < 8; i++) {
#pragma unroll
            for (int j = 0; j < 8; j++) {
                int cand = candBase + tx * 8 + j;
                float dist = xr[i] + cc[cand] - 2.f * acc[i][j];
                if (dist < bestD[i]) { bestD[i] = dist; bestI[i] = cand; }
            }
        }
    }

    if (tid < BM) sBest[tid] = 0xFFFFFFFFFFFFFFFFULL;
    __syncthreads();
#pragma unroll
    for (int i = 0; i < 8; i++) {
        unsigned long long p =
            ((unsigned long long)f2ord(bestD[i]) << 32) | (unsigned int)bestI[i];
        atomicMin(&sBest[ty * 8 + i], p);
    }
    __syncthreads();
    if (tid < BM) atomicMin(&g_best[rowBase + tid], sBest[tid]);
}

// per-row update: residual, agg, xx, loss term, code index, optional final out
__global__ void k_update(const float* __restrict__ x, const float* __restrict__ cb,
                         float* __restrict__ out, float* __restrict__ codes,
                         float* __restrict__ loss, int d) {
    int row = blockIdx.x, t = threadIdx.x;
    unsigned long long p = g_best[row];
    unsigned int idx = (unsigned int)(p & 0xFFFFFFFFu);
    size_t off = (size_t)row * D + t;
    float q = cb[(size_t)idx * D + t];
    float r = g_res[off] - q;
    g_res[off] = r;
    float a = g_agg[off] + q;
    g_agg[off] = a;
    float xv = x[off];
    float diff = xv - a;
    if (d == DEPTH - 1) out[off] = xv + (a - xv);   // STE rounding replica
    float s1 = r * r, s2 = diff * diff;
    blockReduce2(s1, s2);
    if (t == 0) {
        g_xx[row] = s1;
        atomicAdd(loss, s2 * LOSS_SCALE);
        codes[(size_t)row * DEPTH + d] = (float)idx;
        g_best[row] = 0xFFFFFFFFFFFFFFFFULL;        // reset for next depth
    }
}

extern "C" void kernel_launch(void* const* d_in, const int* in_sizes, int n_in,
                              void* d_out, int out_size) {
    const float* x = (const float*)d_in[0];
    const float* cbs = (const float*)d_in[1];
    float* out = (float*)d_out;                      // [N_ROWS*D]
    float* loss = out + (size_t)N_ROWS * D;          // [1]
    float* codes = loss + 1;                         // [N_ROWS*DEPTH] as float

    k_init<<<(N_ROWS * D + 255) / 256, 256>>>(x, loss);
    k_xx<<<N_ROWS, 256>>>(x);
    k_cc<<<DEPTH * K, 256>>>(cbs);

    for (int d = 0; d < DEPTH; d++) {
        const float* cb = cbs + (size_t)d * CB_STRIDE;
        dim3 grid(N_ROWS / BM, K / (BN * CTILES));
        k_argmin<<<grid, 256>>>(cb, d);
        k_update<<<N_ROWS, 256>>>(x, cb, out, codes, loss, d);
    }
}

// round 4
// speedup vs baseline: 4.5058x; 4.5058x over previous
#include <cuda_runtime.h>
#include <cuda_fp16.h>
#include <cstdint>

#define N_ROWS 8192
#define D      256
#define K      8192
#define DEPTH  4
#define CB_STRIDE ((K + 1) * D)
#define LOSS_SCALE (0.25f / (4.0f * 2097152.0f))
#define MARGIN 8e-3f

#define BM 128
#define BN 128
#define BKC 64
#define NCH (D / BKC)               // 4 k-chunks
#define LDH 72                      // smem pitch in halves (64 + 8 pad)
#define PITCHB (LDH * 2)            // 144 bytes
#define TILEB (BM * PITCHB)         // 18432 bytes per tile
#define BOFF  TILEB
#define STAGE (2 * TILEB)           // 36864
#define SMEMT (2 * STAGE)           // 73728

// ---------------- persistent scratch (16B+ aligned: vector access everywhere) ----
__device__ __align__(256) float  g_res[N_ROWS * D];
__device__ __align__(256) float  g_agg[N_ROWS * D];
__device__ __align__(256) __half g_res_h[N_ROWS * D];
__device__ __align__(256) __half g_cb_h[DEPTH * K * D];
__device__ __align__(16)  float  g_cc[DEPTH * K];
__device__ __align__(16)  unsigned long long g_top[N_ROWS * 128];  // 64 tiles x top-2
__device__ __align__(16)  int    g_idx[N_ROWS];

// ---------------- helpers ----------------
__device__ __forceinline__ uint32_t smem_u32(const void* p) {
    uint32_t a;
    asm("{ .reg .u64 t; cvta.to.shared.u64 t, %1; cvt.u32.u64 %0, t; }" : "=r"(a) : "l"(p));
    return a;
}
__device__ __forceinline__ unsigned int f2ord(float f) {
    unsigned int u = __float_as_uint(f);
    return (u & 0x80000000u) ? ~u : (u | 0x80000000u);
}
__device__ __forceinline__ float ord2f(unsigned int o) {
    unsigned int u = (o & 0x80000000u) ? (o & 0x7FFFFFFFu) : ~o;
    return __uint_as_float(u);
}
__device__ __forceinline__ void merge2(unsigned long long& b1, unsigned long long& b2,
                                       unsigned long long o1, unsigned long long o2) {
    if (o1 < b1) { b2 = (b1 < o2) ? b1 : o2; b1 = o1; }
    else if (o1 < b2) { b2 = o1; }
}
__device__ __forceinline__ void push2(unsigned long long& b1, unsigned long long& b2,
                                      unsigned long long k) {
    if (k < b1) { b2 = b1; b1 = k; }
    else if (k < b2) { b2 = k; }
}

__device__ __forceinline__ void cpa16(uint32_t dst, const void* src) {
    asm volatile("cp.async.cg.shared.global [%0], [%1], 16;" :: "r"(dst), "l"(src));
}
#define CP_COMMIT() asm volatile("cp.async.commit_group;" ::: "memory")
#define CP_WAIT(n)  asm volatile("cp.async.wait_group %0;" :: "n"(n) : "memory")

#define LDSM4(r0, r1, r2, r3, a) \
    asm volatile("ldmatrix.sync.aligned.m8n8.x4.shared.b16 {%0,%1,%2,%3}, [%4];" \
                 : "=r"(r0), "=r"(r1), "=r"(r2), "=r"(r3) : "r"(a))

#define MMA16816(c, a, b0, b1) \
    asm volatile("mma.sync.aligned.m16n8k16.row.col.f32.f16.f16.f32 " \
                 "{%0,%1,%2,%3},{%4,%5,%6,%7},{%8,%9},{%0,%1,%2,%3};" \
                 : "+f"((c)[0]), "+f"((c)[1]), "+f"((c)[2]), "+f"((c)[3]) \
                 : "r"((a)[0]), "r"((a)[1]), "r"((a)[2]), "r"((a)[3]), "r"(b0), "r"(b1))

// reduce two values across a 256-thread block; result in thread 0
__device__ __forceinline__ void blockReduce2(float& a, float& b) {
    __shared__ float sa[8], sb2[8];
    int lane = threadIdx.x & 31, w = threadIdx.x >> 5;
#pragma unroll
    for (int o = 16; o > 0; o >>= 1) {
        a += __shfl_down_sync(0xffffffffu, a, o);
        b += __shfl_down_sync(0xffffffffu, b, o);
    }
    if (lane == 0) { sa[w] = a; sb2[w] = b; }
    __syncthreads();
    if (w == 0) {
        a = (lane < 8) ? sa[lane] : 0.f;
        b = (lane < 8) ? sb2[lane] : 0.f;
#pragma unroll
        for (int o = 4; o > 0; o >>= 1) {
            a += __shfl_down_sync(0xffu, a, o);
            b += __shfl_down_sync(0xffu, b, o);
        }
    }
}

// ---------------- setup ----------------
__global__ void k_init(const float* __restrict__ x, float* __restrict__ loss) {
    int i = blockIdx.x * blockDim.x + threadIdx.x;
    if (i < N_ROWS * D) {
        float v = x[i];
        g_res[i] = v; g_agg[i] = 0.f;
        g_res_h[i] = __float2half_rn(v);
    }
    if (i == 0) *loss = 0.f;
}

__global__ void k_cb(const float* __restrict__ cbs) {
    int rid = blockIdx.x;                     // 0 .. DEPTH*K-1
    int dd = rid / K, r = rid % K;
    float v = cbs[(size_t)dd * CB_STRIDE + (size_t)r * D + threadIdx.x];
    g_cb_h[(size_t)rid * D + threadIdx.x] = __float2half_rn(v);
    float a = v * v, b = 0.f;
    blockReduce2(a, b);
    if (threadIdx.x == 0) g_cc[rid] = a;
}

// ---------------- HMMA GEMM + per-CTA top-2 ----------------
// grid = (64, 64), block = 256 (8 warps: 4 row x 2 col)
__global__ void __launch_bounds__(256, 2) k_gemm(int dep) {
    extern __shared__ char smem[];
    const uint32_t sb = smem_u32(smem);
    const int tid = threadIdx.x, lane = tid & 31, wid = tid >> 5;
    const int wm = wid & 3, wn = wid >> 2;
    const int rowBase = blockIdx.x * BM, candBase = blockIdx.y * BN;

    const char* Ag = (const char*)(g_res_h + (size_t)rowBase * D);
    const char* Bg = (const char*)(g_cb_h + ((size_t)dep * K + (size_t)candBase) * D);

    // loader offsets (per-thread invariant)
    const int r0 = tid >> 3, j0 = (tid & 7);
    const uint32_t sA = r0 * PITCHB + j0 * 16;
    const size_t gOff = (size_t)r0 * 512 + j0 * 16;

    float acc[2][8][4];
#pragma unroll
    for (int a = 0; a < 2; a++)
#pragma unroll
        for (int b = 0; b < 8; b++)
#pragma unroll
            for (int c = 0; c < 4; c++) acc[a][b][c] = 0.f;

    // ldmatrix invariant address parts
    const uint32_t aBase = (uint32_t)((wm * 32 + (lane & 15)) * PITCHB + ((lane >> 4) << 3) * 2);
    const uint32_t bBase = (uint32_t)((wn * 64 + (lane & 7) + ((lane >> 4) << 3)) * PITCHB +
                                      (((lane >> 3) & 1) << 3) * 2);

    // preload chunk 0 into stage 0
#pragma unroll
    for (int i = 0; i < 4; i++) {
        uint32_t so = sA + i * 32 * PITCHB;
        size_t go = gOff + (size_t)i * 32 * 512;
        cpa16(sb + so, Ag + go);
        cpa16(sb + BOFF + so, Bg + go);
    }
    CP_COMMIT();

    for (int ch = 0; ch < NCH; ch++) {
        if (ch < NCH - 1) {
            uint32_t stg = ((ch + 1) & 1) * STAGE;
#pragma unroll
            for (int i = 0; i < 4; i++) {
                uint32_t so = sA + i * 32 * PITCHB;
                size_t go = gOff + (size_t)i * 32 * 512 + (ch + 1) * 128;
                cpa16(sb + stg + so, Ag + go);
                cpa16(sb + stg + BOFF + so, Bg + go);
            }
            CP_COMMIT();
            CP_WAIT(1);
        } else {
            CP_WAIT(0);
        }
        __syncthreads();

        const uint32_t stg = (ch & 1) * STAGE;
#pragma unroll
        for (int ks = 0; ks < 4; ks++) {
            uint32_t A0[4], A1[4], Bf[4][4];
            uint32_t aAddr = sb + stg + aBase + ks * 32;
            LDSM4(A0[0], A0[1], A0[2], A0[3], aAddr);
            LDSM4(A1[0], A1[1], A1[2], A1[3], aAddr + 16 * PITCHB);
            uint32_t bAddr = sb + stg + BOFF + bBase + ks * 32;
#pragma unroll
            for (int nb = 0; nb < 4; nb++)
                LDSM4(Bf[nb][0], Bf[nb][1], Bf[nb][2], Bf[nb][3], bAddr + nb * 16 * PITCHB);
#pragma unroll
            for (int nb = 0; nb < 4; nb++) {
                MMA16816(acc[0][nb * 2 + 0], A0, Bf[nb][0], Bf[nb][1]);
                MMA16816(acc[0][nb * 2 + 1], A0, Bf[nb][2], Bf[nb][3]);
                MMA16816(acc[1][nb * 2 + 0], A1, Bf[nb][0], Bf[nb][1]);
                MMA16816(acc[1][nb * 2 + 1], A1, Bf[nb][2], Bf[nb][3]);
            }
        }
        __syncthreads();
    }

    // ---------------- epilogue: per-row top-2 over this CTA's 128 cols ----------------
    unsigned long long* sTop = (unsigned long long*)smem;   // [128][2][2]
    const float* cc = g_cc + (size_t)dep * K;

#pragma unroll
    for (int mb = 0; mb < 2; mb++) {
#pragma unroll
        for (int rb = 0; rb < 2; rb++) {
            unsigned long long b1 = ~0ull, b2 = ~0ull;
#pragma unroll
            for (int nf = 0; nf < 8; nf++) {
                int col = candBase + wn * 64 + nf * 8 + (lane & 3) * 2;
                float2 c2 = *(const float2*)&cc[col];
                float k0 = c2.x - 2.f * acc[mb][nf][rb * 2 + 0];
                float k1 = c2.y - 2.f * acc[mb][nf][rb * 2 + 1];
                push2(b1, b2, ((unsigned long long)f2ord(k0) << 32) | (unsigned int)col);
                push2(b1, b2, ((unsigned long long)f2ord(k1) << 32) | (unsigned int)(col + 1));
            }
#pragma unroll
            for (int off = 1; off <= 2; off <<= 1) {
                unsigned long long o1 = __shfl_xor_sync(0xffffffffu, b1, off);
                unsigned long long o2 = __shfl_xor_sync(0xffffffffu, b2, off);
                merge2(b1, b2, o1, o2);
            }
            if ((lane & 3) == 0) {
                int rl = wm * 32 + mb * 16 + rb * 8 + (lane >> 2);
                sTop[(rl * 2 + wn) * 2 + 0] = b1;
                sTop[(rl * 2 + wn) * 2 + 1] = b2;
            }
        }
    }
    __syncthreads();
    if (tid < 128) {
        unsigned long long p1 = sTop[(tid * 2 + 0) * 2 + 0];
        unsigned long long p2 = sTop[(tid * 2 + 0) * 2 + 1];
        merge2(p1, p2, sTop[(tid * 2 + 1) * 2 + 0], sTop[(tid * 2 + 1) * 2 + 1]);
        size_t go = (size_t)(rowBase + tid) * 128 + blockIdx.y * 2;
        g_top[go + 0] = p1;
        g_top[go + 1] = p2;
    }
}

// ---------------- select: margin test + exact rescore ----------------
__global__ void k_select(const float* __restrict__ cb, int dep) {
    const int row = blockIdx.x, t = threadIdx.x, lane = t & 31, w = t >> 5;
    __shared__ unsigned long long se[128];
    __shared__ unsigned long long sp[4][2];
    __shared__ unsigned long long sbest;
    __shared__ __align__(16) float rs[256];

    unsigned long long e = g_top[(size_t)row * 128 + t];
    se[t] = e;
    unsigned long long p1 = e, p2 = ~0ull;
#pragma unroll
    for (int off = 16; off > 0; off >>= 1) {
        unsigned long long o1 = __shfl_xor_sync(0xffffffffu, p1, off);
        unsigned long long o2 = __shfl_xor_sync(0xffffffffu, p2, off);
        merge2(p1, p2, o1, o2);
    }
    if (lane == 0) { sp[w][0] = p1; sp[w][1] = p2; }
    __syncthreads();
    if (t == 0) {
        p1 = sp[0][0]; p2 = sp[0][1];
#pragma unroll
        for (int i = 1; i < 4; i++) merge2(p1, p2, sp[i][0], sp[i][1]);
        float d1 = ord2f((unsigned int)(p1 >> 32));
        float d2 = ord2f((unsigned int)(p2 >> 32));
        if (d2 - d1 >= MARGIN) {
            g_idx[row] = (int)(p1 & 0xFFFFFFFFu);
            sbest = 0ull;
        } else {
            sbest = ~0ull;
        }
    }
    __syncthreads();
    if (sbest == 0ull) return;

    rs[t] = g_res[(size_t)row * D + t];
    rs[t + 128] = g_res[(size_t)row * D + t + 128];
    __syncthreads();

    unsigned long long best = ~0ull;
    for (int q = w; q < 128; q += 4) {
        int cand = (int)(se[q] & 0xFFFFFFFFu);
        const float* cr = cb + (size_t)cand * D;
        float4 c0 = *(const float4*)&cr[lane * 8];
        float4 c1 = *(const float4*)&cr[lane * 8 + 4];
        float4 x0 = *(const float4*)&rs[lane * 8];
        float4 x1 = *(const float4*)&rs[lane * 8 + 4];
        float p = x0.x * c0.x + x0.y * c0.y + x0.z * c0.z + x0.w * c0.w
                + x1.x * c1.x + x1.y * c1.y + x1.z * c1.z + x1.w * c1.w;
#pragma unroll
        for (int o = 16; o > 0; o >>= 1) p += __shfl_down_sync(0xffffffffu, p, o);
        if (lane == 0) {
            float dist = g_cc[(size_t)dep * K + cand] - 2.f * p;
            unsigned long long key = ((unsigned long long)f2ord(dist) << 32) | (unsigned int)cand;
            if (key < best) best = key;
        }
    }
    if (lane == 0) atomicMin(&sbest, best);
    __syncthreads();
    if (t == 0) g_idx[row] = (int)(sbest & 0xFFFFFFFFu);
}

// ---------------- per-row update ----------------
__global__ void k_update(const float* __restrict__ x, const float* __restrict__ cb,
                         float* __restrict__ out, float* __restrict__ codes,
                         float* __restrict__ loss, int d) {
    int row = blockIdx.x, t = threadIdx.x;
    int idx = g_idx[row];
    size_t off = (size_t)row * D + t;
    float q = cb[(size_t)idx * D + t];
    float r = g_res[off] - q;
    g_res[off] = r;
    g_res_h[off] = __float2half_rn(r);
    float a = g_agg[off] + q;
    g_agg[off] = a;
    float xv = x[off];
    float diff = xv - a;
    if (d == DEPTH - 1) out[off] = xv + (a - xv);
    float s1 = r * r, s2 = diff * diff;
    blockReduce2(s1, s2);
    if (t == 0) {
        atomicAdd(loss, s2 * LOSS_SCALE);
        codes[(size_t)row * DEPTH + d] = (float)idx;
    }
}

extern "C" void kernel_launch(void* const* d_in, const int* in_sizes, int n_in,
                              void* d_out, int out_size) {
    const float* x = (const float*)d_in[0];
    const float* cbs = (const float*)d_in[1];
    float* out = (float*)d_out;
    float* loss = out + (size_t)N_ROWS * D;
    float* codes = loss + 1;

    cudaFuncSetAttribute(k_gemm, cudaFuncAttributeMaxDynamicSharedMemorySize, SMEMT);

    k_init<<<(N_ROWS * D + 255) / 256, 256>>>(x, loss);
    k_cb<<<DEPTH * K, 256>>>(cbs);

    for (int d = 0; d < DEPTH; d++) {
        const float* cb = cbs + (size_t)d * CB_STRIDE;
        dim3 grid(N_ROWS / BM, K / BN);
        k_gemm<<<grid, 256, SMEMT>>>(d);
        k_select<<<N_ROWS, 128>>>(cb, d);
        k_update<<<N_ROWS, 256>>>(x, cb, out, codes, loss, d);
    }
}

// round 5
// speedup vs baseline: 4.7887x; 1.0628x over previous
#include <cuda_runtime.h>
#include <cuda_fp16.h>
#include <cstdint>

#define N_ROWS 8192
#define D      256
#define K      8192
#define DEPTH  4
#define CB_STRIDE ((K + 1) * D)
#define LOSS_SCALE (0.25f / (4.0f * 2097152.0f))
#define MARGIN 8e-3f

#define BM 128
#define BN 128
#define NCH 4                       // 4 k-chunks of 64 halves
#define LDH 72                      // smem pitch in halves (64 + 8 pad)
#define PITCHB (LDH * 2)            // 144 bytes
#define TILEB (BM * PITCHB)         // 18432 bytes per tile
#define BOFF  TILEB
#define STAGE (2 * TILEB)           // 36864
#define NSTG  3
#define SMEMT (NSTG * STAGE)        // 110592

// ---------------- persistent scratch (aligned: vector access everywhere) ----
__device__ __align__(256) float  g_res[N_ROWS * D];
__device__ __align__(256) float  g_agg[N_ROWS * D];
__device__ __align__(256) __half g_res_h[N_ROWS * D];
__device__ __align__(256) __half g_cb_h[DEPTH * K * D];
__device__ __align__(16)  float  g_cc[DEPTH * K];
__device__ __align__(16)  unsigned long long g_top[N_ROWS * 128];  // 64 tiles x top-2
__device__ __align__(16)  int    g_idx[N_ROWS];

// ---------------- helpers ----------------
__device__ __forceinline__ uint32_t smem_u32(const void* p) {
    uint32_t a;
    asm("{ .reg .u64 t; cvta.to.shared.u64 t, %1; cvt.u32.u64 %0, t; }" : "=r"(a) : "l"(p));
    return a;
}
__device__ __forceinline__ unsigned int f2ord(float f) {
    unsigned int u = __float_as_uint(f);
    return (u & 0x80000000u) ? ~u : (u | 0x80000000u);
}
__device__ __forceinline__ float ord2f(unsigned int o) {
    unsigned int u = (o & 0x80000000u) ? (o & 0x7FFFFFFFu) : ~o;
    return __uint_as_float(u);
}
__device__ __forceinline__ void merge2(unsigned long long& b1, unsigned long long& b2,
                                       unsigned long long o1, unsigned long long o2) {
    if (o1 < b1) { b2 = (b1 < o2) ? b1 : o2; b1 = o1; }
    else if (o1 < b2) { b2 = o1; }
}
__device__ __forceinline__ void push2(unsigned long long& b1, unsigned long long& b2,
                                      unsigned long long k) {
    if (k < b1) { b2 = b1; b1 = k; }
    else if (k < b2) { b2 = k; }
}

__device__ __forceinline__ void cpa16(uint32_t dst, const void* src) {
    asm volatile("cp.async.cg.shared.global [%0], [%1], 16;" :: "r"(dst), "l"(src));
}
#define CP_COMMIT() asm volatile("cp.async.commit_group;" ::: "memory")
#define CP_WAIT(n)  asm volatile("cp.async.wait_group %0;" :: "n"(n) : "memory")

#define LDSM4(r0, r1, r2, r3, a) \
    asm volatile("ldmatrix.sync.aligned.m8n8.x4.shared.b16 {%0,%1,%2,%3}, [%4];" \
                 : "=r"(r0), "=r"(r1), "=r"(r2), "=r"(r3) : "r"(a))

#define MMA16816(c, a, b0, b1) \
    asm volatile("mma.sync.aligned.m16n8k16.row.col.f32.f16.f16.f32 " \
                 "{%0,%1,%2,%3},{%4,%5,%6,%7},{%8,%9},{%0,%1,%2,%3};" \
                 : "+f"((c)[0]), "+f"((c)[1]), "+f"((c)[2]), "+f"((c)[3]) \
                 : "r"((a)[0]), "r"((a)[1]), "r"((a)[2]), "r"((a)[3]), "r"(b0), "r"(b1))

// reduce two values across a 256-thread block; result in thread 0
__device__ __forceinline__ void blockReduce2_256(float& a, float& b) {
    __shared__ float sa[8], sb2[8];
    int lane = threadIdx.x & 31, w = threadIdx.x >> 5;
#pragma unroll
    for (int o = 16; o > 0; o >>= 1) {
        a += __shfl_down_sync(0xffffffffu, a, o);
        b += __shfl_down_sync(0xffffffffu, b, o);
    }
    if (lane == 0) { sa[w] = a; sb2[w] = b; }
    __syncthreads();
    if (w == 0) {
        a = (lane < 8) ? sa[lane] : 0.f;
        b = (lane < 8) ? sb2[lane] : 0.f;
#pragma unroll
        for (int o = 4; o > 0; o >>= 1) {
            a += __shfl_down_sync(0xffu, a, o);
            b += __shfl_down_sync(0xffu, b, o);
        }
    }
}

// ---------------- setup ----------------
__global__ void k_init(const float* __restrict__ x, float* __restrict__ loss) {
    int i = blockIdx.x * blockDim.x + threadIdx.x;
    if (i < N_ROWS * D) {
        float v = x[i];
        g_res[i] = v; g_agg[i] = 0.f;
        g_res_h[i] = __float2half_rn(v);
    }
    if (i == 0) *loss = 0.f;
}

__global__ void k_cb(const float* __restrict__ cbs) {
    int rid = blockIdx.x;                     // 0 .. DEPTH*K-1
    int dd = rid / K, r = rid % K;
    float v = cbs[(size_t)dd * CB_STRIDE + (size_t)r * D + threadIdx.x];
    g_cb_h[(size_t)rid * D + threadIdx.x] = __float2half_rn(v);
    float a = v * v, b = 0.f;
    blockReduce2_256(a, b);
    if (threadIdx.x == 0) g_cc[rid] = a;
}

// ---------------- HMMA GEMM + per-CTA top-2 ----------------
// grid = (64, 64), block = 256 (8 warps: 4 row x 2 col), 3-stage cp.async pipe
__global__ void __launch_bounds__(256, 2) k_gemm(int dep) {
    extern __shared__ char smem[];
    const uint32_t sb = smem_u32(smem);
    const int tid = threadIdx.x, lane = tid & 31, wid = tid >> 5;
    const int wm = wid & 3, wn = wid >> 2;
    const int rowBase = blockIdx.x * BM, candBase = blockIdx.y * BN;

    const char* Ag = (const char*)(g_res_h + (size_t)rowBase * D);
    const char* Bg = (const char*)(g_cb_h + ((size_t)dep * K + (size_t)candBase) * D);

    // loader offsets (per-thread invariant)
    const int r0 = tid >> 3, j0 = (tid & 7);
    const uint32_t sA = r0 * PITCHB + j0 * 16;
    const size_t gOff = (size_t)r0 * 512 + j0 * 16;

    float acc[2][8][4];
#pragma unroll
    for (int a = 0; a < 2; a++)
#pragma unroll
        for (int b = 0; b < 8; b++)
#pragma unroll
            for (int c = 0; c < 4; c++) acc[a][b][c] = 0.f;

    // ldmatrix invariant address parts
    const uint32_t aBase = (uint32_t)((wm * 32 + (lane & 15)) * PITCHB + ((lane >> 4) << 3) * 2);
    const uint32_t bBase = (uint32_t)((wn * 64 + (lane & 7) + ((lane >> 4) << 3)) * PITCHB +
                                      (((lane >> 3) & 1) << 3) * 2);

    // prologue: preload chunks 0 and 1 into stages 0 and 1
#pragma unroll
    for (int pc = 0; pc < 2; pc++) {
        uint32_t stg = pc * STAGE;
#pragma unroll
        for (int i = 0; i < 4; i++) {
            uint32_t so = sA + i * 32 * PITCHB;
            size_t go = gOff + (size_t)i * 32 * 512 + pc * 128;
            cpa16(sb + stg + so, Ag + go);
            cpa16(sb + stg + BOFF + so, Bg + go);
        }
        CP_COMMIT();
    }

#pragma unroll
    for (int ch = 0; ch < NCH; ch++) {
        if (ch + 2 < NCH) {
            uint32_t stg = ((ch + 2) % NSTG) * STAGE;
#pragma unroll
            for (int i = 0; i < 4; i++) {
                uint32_t so = sA + i * 32 * PITCHB;
                size_t go = gOff + (size_t)i * 32 * 512 + (ch + 2) * 128;
                cpa16(sb + stg + so, Ag + go);
                cpa16(sb + stg + BOFF + so, Bg + go);
            }
            CP_COMMIT();
            CP_WAIT(2);
        } else if (ch + 2 == NCH) {
            CP_WAIT(1);
        } else {
            CP_WAIT(0);
        }
        __syncthreads();

        const uint32_t stg = (ch % NSTG) * STAGE;
#pragma unroll
        for (int ks = 0; ks < 4; ks++) {
            uint32_t A0[4], A1[4], Bf[4][4];
            uint32_t aAddr = sb + stg + aBase + ks * 32;
            LDSM4(A0[0], A0[1], A0[2], A0[3], aAddr);
            LDSM4(A1[0], A1[1], A1[2], A1[3], aAddr + 16 * PITCHB);
            uint32_t bAddr = sb + stg + BOFF + bBase + ks * 32;
#pragma unroll
            for (int nb = 0; nb < 4; nb++)
                LDSM4(Bf[nb][0], Bf[nb][1], Bf[nb][2], Bf[nb][3], bAddr + nb * 16 * PITCHB);
#pragma unroll
            for (int nb = 0; nb < 4; nb++) {
                MMA16816(acc[0][nb * 2 + 0], A0, Bf[nb][0], Bf[nb][1]);
                MMA16816(acc[0][nb * 2 + 1], A0, Bf[nb][2], Bf[nb][3]);
                MMA16816(acc[1][nb * 2 + 0], A1, Bf[nb][0], Bf[nb][1]);
                MMA16816(acc[1][nb * 2 + 1], A1, Bf[nb][2], Bf[nb][3]);
            }
        }
        __syncthreads();
    }

    // ---------------- epilogue: per-row top-2 over this CTA's 128 cols ----------------
    unsigned long long* sTop = (unsigned long long*)smem;   // [128][2][2]
    const float* cc = g_cc + (size_t)dep * K;

#pragma unroll
    for (int mb = 0; mb < 2; mb++) {
#pragma unroll
        for (int rb = 0; rb < 2; rb++) {
            unsigned long long b1 = ~0ull, b2 = ~0ull;
#pragma unroll
            for (int nf = 0; nf < 8; nf++) {
                int col = candBase + wn * 64 + nf * 8 + (lane & 3) * 2;
                float2 c2 = *(const float2*)&cc[col];
                float k0 = c2.x - 2.f * acc[mb][nf][rb * 2 + 0];
                float k1 = c2.y - 2.f * acc[mb][nf][rb * 2 + 1];
                push2(b1, b2, ((unsigned long long)f2ord(k0) << 32) | (unsigned int)col);
                push2(b1, b2, ((unsigned long long)f2ord(k1) << 32) | (unsigned int)(col + 1));
            }
#pragma unroll
            for (int off = 1; off <= 2; off <<= 1) {
                unsigned long long o1 = __shfl_xor_sync(0xffffffffu, b1, off);
                unsigned long long o2 = __shfl_xor_sync(0xffffffffu, b2, off);
                merge2(b1, b2, o1, o2);
            }
            if ((lane & 3) == 0) {
                int rl = wm * 32 + mb * 16 + rb * 8 + (lane >> 2);
                sTop[(rl * 2 + wn) * 2 + 0] = b1;
                sTop[(rl * 2 + wn) * 2 + 1] = b2;
            }
        }
    }
    __syncthreads();
    if (tid < 128) {
        unsigned long long p1 = sTop[(tid * 2 + 0) * 2 + 0];
        unsigned long long p2 = sTop[(tid * 2 + 0) * 2 + 1];
        merge2(p1, p2, sTop[(tid * 2 + 1) * 2 + 0], sTop[(tid * 2 + 1) * 2 + 1]);
        size_t go = (size_t)(rowBase + tid) * 128 + blockIdx.y * 2;
        g_top[go + 0] = p1;
        g_top[go + 1] = p2;
    }
}

// ---------------- fused select (margin + exact rescore) + update ----------------
// grid = N_ROWS, block = 128
__global__ void k_finish(const float* __restrict__ x, const float* __restrict__ cb,
                         float* __restrict__ out, float* __restrict__ codes,
                         float* __restrict__ loss, int dep) {
    const int row = blockIdx.x, t = threadIdx.x, lane = t & 31, w = t >> 5;
    __shared__ unsigned long long se[128];
    __shared__ unsigned long long sp[4][2];
    __shared__ unsigned long long sbest;
    __shared__ __align__(16) float rs[256];
    __shared__ int sidx;
    __shared__ float sred[2][4];

    // ---- select ----
    unsigned long long e = g_top[(size_t)row * 128 + t];
    se[t] = e;
    unsigned long long p1 = e, p2 = ~0ull;
#pragma unroll
    for (int off = 16; off > 0; off >>= 1) {
        unsigned long long o1 = __shfl_xor_sync(0xffffffffu, p1, off);
        unsigned long long o2 = __shfl_xor_sync(0xffffffffu, p2, off);
        merge2(p1, p2, o1, o2);
    }
    if (lane == 0) { sp[w][0] = p1; sp[w][1] = p2; }
    __syncthreads();
    if (t == 0) {
        p1 = sp[0][0]; p2 = sp[0][1];
#pragma unroll
        for (int i = 1; i < 4; i++) merge2(p1, p2, sp[i][0], sp[i][1]);
        float d1 = ord2f((unsigned int)(p1 >> 32));
        float d2 = ord2f((unsigned int)(p2 >> 32));
        if (d2 - d1 >= MARGIN) {
            sidx = (int)(p1 & 0xFFFFFFFFu);
            sbest = 0ull;
        } else {
            sbest = ~0ull;
        }
    }
    __syncthreads();

    // residual row into shared (needed by both rescore and update paths)
    float r0v = g_res[(size_t)row * D + t];
    float r1v = g_res[(size_t)row * D + t + 128];
    rs[t] = r0v;
    rs[t + 128] = r1v;
    __syncthreads();

    if (sbest != 0ull) {
        unsigned long long best = ~0ull;
        for (int q = w; q < 128; q += 4) {
            int cand = (int)(se[q] & 0xFFFFFFFFu);
            const float* cr = cb + (size_t)cand * D;
            float4 c0 = *(const float4*)&cr[lane * 8];
            float4 c1 = *(const float4*)&cr[lane * 8 + 4];
            float4 x0 = *(const float4*)&rs[lane * 8];
            float4 x1 = *(const float4*)&rs[lane * 8 + 4];
            float p = x0.x * c0.x + x0.y * c0.y + x0.z * c0.z + x0.w * c0.w
                    + x1.x * c1.x + x1.y * c1.y + x1.z * c1.z + x1.w * c1.w;
#pragma unroll
            for (int o = 16; o > 0; o >>= 1) p += __shfl_down_sync(0xffffffffu, p, o);
            if (lane == 0) {
                float dist = g_cc[(size_t)dep * K + cand] - 2.f * p;
                unsigned long long key =
                    ((unsigned long long)f2ord(dist) << 32) | (unsigned int)cand;
                if (key < best) best = key;
            }
        }
        if (lane == 0) atomicMin(&sbest, best);
        __syncthreads();
        if (t == 0) sidx = (int)(sbest & 0xFFFFFFFFu);
        __syncthreads();
    }

    // ---- update (each thread owns elements t and t+128) ----
    const int idx = sidx;
    size_t off0 = (size_t)row * D + t;
    size_t off1 = off0 + 128;
    float q0 = cb[(size_t)idx * D + t];
    float q1 = cb[(size_t)idx * D + t + 128];
    float nr0 = r0v - q0, nr1 = r1v - q1;
    g_res[off0] = nr0; g_res[off1] = nr1;
    g_res_h[off0] = __float2half_rn(nr0);
    g_res_h[off1] = __float2half_rn(nr1);
    float a0 = g_agg[off0] + q0, a1 = g_agg[off1] + q1;
    g_agg[off0] = a0; g_agg[off1] = a1;
    float xv0 = x[off0], xv1 = x[off1];
    float df0 = xv0 - a0, df1 = xv1 - a1;
    if (dep == DEPTH - 1) { out[off0] = xv0 + (a0 - xv0); out[off1] = xv1 + (a1 - xv1); }

    float s2 = df0 * df0 + df1 * df1;
#pragma unroll
    for (int o = 16; o > 0; o >>= 1) s2 += __shfl_down_sync(0xffffffffu, s2, o);
    if (lane == 0) sred[0][w] = s2;
    __syncthreads();
    if (t == 0) {
        atomicAdd(loss, (sred[0][0] + sred[0][1] + sred[0][2] + sred[0][3]) * LOSS_SCALE);
        codes[(size_t)row * DEPTH + dep] = (float)idx;
    }
}

extern "C" void kernel_launch(void* const* d_in, const int* in_sizes, int n_in,
                              void* d_out, int out_size) {
    const float* x = (const float*)d_in[0];
    const float* cbs = (const float*)d_in[1];
    float* out = (float*)d_out;
    float* loss = out + (size_t)N_ROWS * D;
    float* codes = loss + 1;

    cudaFuncSetAttribute(k_gemm, cudaFuncAttributeMaxDynamicSharedMemorySize, SMEMT);

    k_init<<<(N_ROWS * D + 255) / 256, 256>>>(x, loss);
    k_cb<<<DEPTH * K, 256>>>(cbs);

    for (int d = 0; d < DEPTH; d++) {
        const float* cb = cbs + (size_t)d * CB_STRIDE;
        dim3 grid(N_ROWS / BM, K / BN);
        k_gemm<<<grid, 256, SMEMT>>>(d);
        k_finish<<<N_ROWS, 128>>>(x, cb, out, codes, loss, d);
    }
}

// round 7
// speedup vs baseline: 5.3719x; 1.1218x over previous
#include <cuda_runtime.h>
#include <cuda_fp16.h>
#include <cstdint>

#define N_ROWS 8192
#define D      256
#define K      8192
#define DEPTH  4
#define CB_STRIDE ((K + 1) * D)
#define LOSS_SCALE (0.25f / (4.0f * 2097152.0f))
#define MARGIN 8e-3f

#define BM 128
#define BN 128
#define NCH 4                       // 4 k-chunks of 64 halves
#define LDH 72                      // smem pitch in halves (64 + 8 pad)
#define PITCHB (LDH * 2)            // 144 bytes
#define TILEB (BM * PITCHB)         // 18432 bytes per tile
#define BOFF  TILEB
#define STAGE (2 * TILEB)           // 36864
#define NSTG  3
#define SMEMT (NSTG * STAGE)        // 110592

// ---------------- persistent scratch (aligned: vector access everywhere) ----
__device__ __align__(256) float  g_res[N_ROWS * D];
__device__ __align__(256) float  g_agg[N_ROWS * D];
__device__ __align__(256) __half g_res_h[N_ROWS * D];
__device__ __align__(256) __half g_cb_h[DEPTH * K * D];
__device__ __align__(16)  float  g_cc[DEPTH * K];
__device__ __align__(16)  unsigned long long g_top[N_ROWS * 128];  // 64 tiles x top-2

// ---------------- helpers ----------------
__device__ __forceinline__ uint32_t smem_u32(const void* p) {
    uint32_t a;
    asm("{ .reg .u64 t; cvta.to.shared.u64 t, %1; cvt.u32.u64 %0, t; }" : "=r"(a) : "l"(p));
    return a;
}
__device__ __forceinline__ uint32_t h2_as_u32(__half2 h) {
    return *reinterpret_cast<uint32_t*>(&h);
}
__device__ __forceinline__ unsigned int f2ord(float f) {
    unsigned int u = __float_as_uint(f);
    return (u & 0x80000000u) ? ~u : (u | 0x80000000u);
}
__device__ __forceinline__ float ord2f(unsigned int o) {
    unsigned int u = (o & 0x80000000u) ? (o & 0x7FFFFFFFu) : ~o;
    return __uint_as_float(u);
}
__device__ __forceinline__ void merge2(unsigned long long& b1, unsigned long long& b2,
                                       unsigned long long o1, unsigned long long o2) {
    if (o1 < b1) { b2 = (b1 < o2) ? b1 : o2; b1 = o1; }
    else if (o1 < b2) { b2 = o1; }
}
__device__ __forceinline__ void push2(unsigned long long& b1, unsigned long long& b2,
                                      unsigned long long k) {
    if (k < b1) { b2 = b1; b1 = k; }
    else if (k < b2) { b2 = k; }
}

__device__ __forceinline__ void cpa16(uint32_t dst, const void* src) {
    asm volatile("cp.async.cg.shared.global [%0], [%1], 16;" :: "r"(dst), "l"(src));
}
#define CP_COMMIT() asm volatile("cp.async.commit_group;" ::: "memory")
#define CP_WAIT(n)  asm volatile("cp.async.wait_group %0;" :: "n"(n) : "memory")

#define LDSM4(r0, r1, r2, r3, a) \
    asm volatile("ldmatrix.sync.aligned.m8n8.x4.shared.b16 {%0,%1,%2,%3}, [%4];" \
                 : "=r"(r0), "=r"(r1), "=r"(r2), "=r"(r3) : "r"(a))

#define MMA16816(c, a, b0, b1) \
    asm volatile("mma.sync.aligned.m16n8k16.row.col.f32.f16.f16.f32 " \
                 "{%0,%1,%2,%3},{%4,%5,%6,%7},{%8,%9},{%0,%1,%2,%3};" \
                 : "+f"((c)[0]), "+f"((c)[1]), "+f"((c)[2]), "+f"((c)[3]) \
                 : "r"((a)[0]), "r"((a)[1]), "r"((a)[2]), "r"((a)[3]), "r"(b0), "r"(b1))

// reduce two values across a 256-thread block; result in thread 0
__device__ __forceinline__ void blockReduce2_256(float& a, float& b) {
    __shared__ float sa[8], sb2[8];
    int lane = threadIdx.x & 31, w = threadIdx.x >> 5;
#pragma unroll
    for (int o = 16; o > 0; o >>= 1) {
        a += __shfl_down_sync(0xffffffffu, a, o);
        b += __shfl_down_sync(0xffffffffu, b, o);
    }
    if (lane == 0) { sa[w] = a; sb2[w] = b; }
    __syncthreads();
    if (w == 0) {
        a = (lane < 8) ? sa[lane] : 0.f;
        b = (lane < 8) ? sb2[lane] : 0.f;
#pragma unroll
        for (int o = 4; o > 0; o >>= 1) {
            a += __shfl_down_sync(0xffu, a, o);
            b += __shfl_down_sync(0xffu, b, o);
        }
    }
}

// ---------------- setup ----------------
__global__ void k_init(const float* __restrict__ x) {
    int i = blockIdx.x * blockDim.x + threadIdx.x;
    if (i < N_ROWS * D) {
        float v = x[i];
        g_res[i] = v; g_agg[i] = 0.f;
        g_res_h[i] = __float2half_rn(v);
    }
}

__global__ void k_cb(const float* __restrict__ cbs) {
    int rid = blockIdx.x;                     // 0 .. DEPTH*K-1
    int dd = rid / K, r = rid % K;
    float v = cbs[(size_t)dd * CB_STRIDE + (size_t)r * D + threadIdx.x];
    g_cb_h[(size_t)rid * D + threadIdx.x] = __float2half_rn(v);
    float a = v * v, b = 0.f;
    blockReduce2_256(a, b);
    if (threadIdx.x == 0) g_cc[rid] = a;
}

__global__ void k_zero(float* __restrict__ loss) {
    if (threadIdx.x == 0) *loss = 0.f;
}

// ---------------- HMMA GEMM + per-CTA top-2 ----------------
// grid = (64, 64), block = 256 (8 warps: 4 row x 2 col), 3-stage cp.async pipe
__global__ void __launch_bounds__(256, 2) k_gemm(int dep) {
    extern __shared__ char smem[];
    const uint32_t sb = smem_u32(smem);
    const int tid = threadIdx.x, lane = tid & 31, wid = tid >> 5;
    const int wm = wid & 3, wn = wid >> 2;
    const int rowBase = blockIdx.x * BM, candBase = blockIdx.y * BN;

    const char* Ag = (const char*)(g_res_h + (size_t)rowBase * D);
    const char* Bg = (const char*)(g_cb_h + ((size_t)dep * K + (size_t)candBase) * D);

    const int r0 = tid >> 3, j0 = (tid & 7);
    const uint32_t sA = r0 * PITCHB + j0 * 16;
    const size_t gOff = (size_t)r0 * 512 + j0 * 16;

    float acc[2][8][4];
#pragma unroll
    for (int a = 0; a < 2; a++)
#pragma unroll
        for (int b = 0; b < 8; b++)
#pragma unroll
            for (int c = 0; c < 4; c++) acc[a][b][c] = 0.f;

    const uint32_t aBase = (uint32_t)((wm * 32 + (lane & 15)) * PITCHB + ((lane >> 4) << 3) * 2);
    const uint32_t bBase = (uint32_t)((wn * 64 + (lane & 7) + ((lane >> 4) << 3)) * PITCHB +
                                      (((lane >> 3) & 1) << 3) * 2);

    // prologue: preload chunks 0 and 1 into stages 0 and 1
#pragma unroll
    for (int pc = 0; pc < 2; pc++) {
        uint32_t stg = pc * STAGE;
#pragma unroll
        for (int i = 0; i < 4; i++) {
            uint32_t so = sA + i * 32 * PITCHB;
            size_t go = gOff + (size_t)i * 32 * 512 + pc * 128;
            cpa16(sb + stg + so, Ag + go);
            cpa16(sb + stg + BOFF + so, Bg + go);
        }
        CP_COMMIT();
    }

#pragma unroll
    for (int ch = 0; ch < NCH; ch++) {
        if (ch + 2 < NCH) {
            uint32_t stg = ((ch + 2) % NSTG) * STAGE;
#pragma unroll
            for (int i = 0; i < 4; i++) {
                uint32_t so = sA + i * 32 * PITCHB;
                size_t go = gOff + (size_t)i * 32 * 512 + (ch + 2) * 128;
                cpa16(sb + stg + so, Ag + go);
                cpa16(sb + stg + BOFF + so, Bg + go);
            }
            CP_COMMIT();
            CP_WAIT(2);
        } else if (ch + 2 == NCH) {
            CP_WAIT(1);
        } else {
            CP_WAIT(0);
        }
        __syncthreads();

        const uint32_t stg = (ch % NSTG) * STAGE;
#pragma unroll
        for (int ks = 0; ks < 4; ks++) {
            uint32_t A0[4], A1[4], Bf[4][4];
            uint32_t aAddr = sb + stg + aBase + ks * 32;
            LDSM4(A0[0], A0[1], A0[2], A0[3], aAddr);
            LDSM4(A1[0], A1[1], A1[2], A1[3], aAddr + 16 * PITCHB);
            uint32_t bAddr = sb + stg + BOFF + bBase + ks * 32;
#pragma unroll
            for (int nb = 0; nb < 4; nb++)
                LDSM4(Bf[nb][0], Bf[nb][1], Bf[nb][2], Bf[nb][3], bAddr + nb * 16 * PITCHB);
#pragma unroll
            for (int nb = 0; nb < 4; nb++) {
                MMA16816(acc[0][nb * 2 + 0], A0, Bf[nb][0], Bf[nb][1]);
                MMA16816(acc[0][nb * 2 + 1], A0, Bf[nb][2], Bf[nb][3]);
                MMA16816(acc[1][nb * 2 + 0], A1, Bf[nb][0], Bf[nb][1]);
                MMA16816(acc[1][nb * 2 + 1], A1, Bf[nb][2], Bf[nb][3]);
            }
        }
        __syncthreads();
    }

    // epilogue: per-row top-2 over this CTA's 128 cols
    unsigned long long* sTop = (unsigned long long*)smem;   // [128][2][2]
    const float* cc = g_cc + (size_t)dep * K;

#pragma unroll
    for (int mb = 0; mb < 2; mb++) {
#pragma unroll
        for (int rb = 0; rb < 2; rb++) {
            unsigned long long b1 = ~0ull, b2 = ~0ull;
#pragma unroll
            for (int nf = 0; nf < 8; nf++) {
                int col = candBase + wn * 64 + nf * 8 + (lane & 3) * 2;
                float2 c2 = *(const float2*)&cc[col];
                float k0 = c2.x - 2.f * acc[mb][nf][rb * 2 + 0];
                float k1 = c2.y - 2.f * acc[mb][nf][rb * 2 + 1];
                push2(b1, b2, ((unsigned long long)f2ord(k0) << 32) | (unsigned int)col);
                push2(b1, b2, ((unsigned long long)f2ord(k1) << 32) | (unsigned int)(col + 1));
            }
#pragma unroll
            for (int off = 1; off <= 2; off <<= 1) {
                unsigned long long o1 = __shfl_xor_sync(0xffffffffu, b1, off);
                unsigned long long o2 = __shfl_xor_sync(0xffffffffu, b2, off);
                merge2(b1, b2, o1, o2);
            }
            if ((lane & 3) == 0) {
                int rl = wm * 32 + mb * 16 + rb * 8 + (lane >> 2);
                sTop[(rl * 2 + wn) * 2 + 0] = b1;
                sTop[(rl * 2 + wn) * 2 + 1] = b2;
            }
        }
    }
    __syncthreads();
    if (tid < 128) {
        unsigned long long p1 = sTop[(tid * 2 + 0) * 2 + 0];
        unsigned long long p2 = sTop[(tid * 2 + 0) * 2 + 1];
        merge2(p1, p2, sTop[(tid * 2 + 1) * 2 + 0], sTop[(tid * 2 + 1) * 2 + 1]);
        size_t go = (size_t)(rowBase + tid) * 128 + blockIdx.y * 2;
        g_top[go + 0] = p1;
        g_top[go + 1] = p2;
    }
}

// ---------------- fused select + rescore + update: warp per row ----------------
// grid = N_ROWS/8 = 1024, block = 256 (8 warps)
__global__ void __launch_bounds__(256) k_finish(
        const float* __restrict__ x, const float* __restrict__ cb,
        float* __restrict__ out, float* __restrict__ codes,
        float* __restrict__ loss, int dep) {
    const int w = threadIdx.x >> 5, lane = threadIdx.x & 31;
    const int row = blockIdx.x * 8 + w;
    __shared__ unsigned long long se[8][128];
    __shared__ int sql[8][128];
    __shared__ float wloss[8];

    // ---- load per-row candidate entries, warp top-2 ----
    const unsigned long long* gt = g_top + (size_t)row * 128;
    unsigned long long b1 = ~0ull, b2 = ~0ull;
#pragma unroll
    for (int i = 0; i < 4; i++) {
        unsigned long long e = gt[lane + i * 32];
        se[w][lane + i * 32] = e;
        push2(b1, b2, e);
    }
#pragma unroll
    for (int off = 16; off > 0; off >>= 1) {
        unsigned long long o1 = __shfl_xor_sync(0xffffffffu, b1, off);
        unsigned long long o2 = __shfl_xor_sync(0xffffffffu, b2, off);
        merge2(b1, b2, o1, o2);
    }
    float d1 = ord2f((unsigned int)(b1 >> 32));
    float d2 = ord2f((unsigned int)(b2 >> 32));
    int idx = (int)(b1 & 0xFFFFFFFFu);

    // residual row (registers; also reused by update)
    const float4* rr = (const float4*)(g_res + (size_t)row * D);
    float4 r0 = rr[lane * 2], r1 = rr[lane * 2 + 1];

    // ---- exact rescore when ambiguous ----
    if (d2 - d1 < MARGIN) {
        const float thr = d1 + MARGIN;
        int nq = 0;
        __syncwarp();
#pragma unroll
        for (int i = 0; i < 4; i++) {
            unsigned long long e = se[w][lane + i * 32];
            bool qf = ord2f((unsigned int)(e >> 32)) <= thr;
            unsigned m = __ballot_sync(0xffffffffu, qf);
            if (qf) {
                int pos = nq + __popc(m & ((1u << lane) - 1u));
                sql[w][pos] = (int)(e & 0xFFFFFFFFu);
            }
            nq += __popc(m);
        }
        __syncwarp();
        unsigned long long best = ~0ull;
        const float* ccd = g_cc + (size_t)dep * K;
        for (int q = 0; q < nq; q++) {
            int cand = sql[w][q];
            const float4* cr = (const float4*)(cb + (size_t)cand * D);
            float4 c0 = cr[lane * 2], c1 = cr[lane * 2 + 1];
            float p = r0.x * c0.x + r0.y * c0.y + r0.z * c0.z + r0.w * c0.w
                    + r1.x * c1.x + r1.y * c1.y + r1.z * c1.z + r1.w * c1.w;
#pragma unroll
            for (int o = 16; o > 0; o >>= 1) p += __shfl_xor_sync(0xffffffffu, p, o);
            float dist = ccd[cand] - 2.f * p;
            unsigned long long key =
                ((unsigned long long)f2ord(dist) << 32) | (unsigned int)cand;
            if (key < best) best = key;
        }
        idx = (int)(best & 0xFFFFFFFFu);
    }

    // ---- update: each lane owns 8 contiguous elements ----
    const size_t o4 = (size_t)row * (D / 4) + lane * 2;
    const float4* cbv = (const float4*)(cb + (size_t)idx * D);
    float4 q0 = cbv[lane * 2], q1 = cbv[lane * 2 + 1];
    float4 a0 = ((const float4*)g_agg)[o4], a1 = ((const float4*)g_agg)[o4 + 1];
    a0.x += q0.x; a0.y += q0.y; a0.z += q0.z; a0.w += q0.w;
    a1.x += q1.x; a1.y += q1.y; a1.z += q1.z; a1.w += q1.w;
    float4 x0 = ((const float4*)x)[o4], x1 = ((const float4*)x)[o4 + 1];

    if (dep < DEPTH - 1) {
        float4 n0, n1;
        n0.x = r0.x - q0.x; n0.y = r0.y - q0.y; n0.z = r0.z - q0.z; n0.w = r0.w - q0.w;
        n1.x = r1.x - q1.x; n1.y = r1.y - q1.y; n1.z = r1.z - q1.z; n1.w = r1.w - q1.w;
        ((float4*)g_res)[o4] = n0;
        ((float4*)g_res)[o4 + 1] = n1;
        uint4 hh;
        hh.x = h2_as_u32(__float22half2_rn(make_float2(n0.x, n0.y)));
        hh.y = h2_as_u32(__float22half2_rn(make_float2(n0.z, n0.w)));
        hh.z = h2_as_u32(__float22half2_rn(make_float2(n1.x, n1.y)));
        hh.w = h2_as_u32(__float22half2_rn(make_float2(n1.z, n1.w)));
        *(uint4*)(g_res_h + (size_t)row * D + lane * 8) = hh;
        ((float4*)g_agg)[o4] = a0;
        ((float4*)g_agg)[o4 + 1] = a1;
    } else {
        float4 ov0, ov1;
        ov0.x = x0.x + (a0.x - x0.x); ov0.y = x0.y + (a0.y - x0.y);
        ov0.z = x0.z + (a0.z - x0.z); ov0.w = x0.w + (a0.w - x0.w);
        ov1.x = x1.x + (a1.x - x1.x); ov1.y = x1.y + (a1.y - x1.y);
        ov1.z = x1.z + (a1.z - x1.z); ov1.w = x1.w + (a1.w - x1.w);
        ((float4*)out)[o4] = ov0;
        ((float4*)out)[o4 + 1] = ov1;
    }

    float d0x = x0.x - a0.x, d0y = x0.y - a0.y, d0z = x0.z - a0.z, d0w = x0.w - a0.w;
    float d1x = x1.x - a1.x, d1y = x1.y - a1.y, d1z = x1.z - a1.z, d1w = x1.w - a1.w;
    float s2 = d0x * d0x + d0y * d0y + d0z * d0z + d0w * d0w
             + d1x * d1x + d1y * d1y + d1z * d1z + d1w * d1w;
#pragma unroll
    for (int o = 16; o > 0; o >>= 1) s2 += __shfl_down_sync(0xffffffffu, s2, o);
    if (lane == 0) {
        wloss[w] = s2;
        codes[(size_t)row * DEPTH + dep] = (float)idx;
    }
    __syncthreads();
    if (threadIdx.x == 0) {
        float t = 0.f;
#pragma unroll
        for (int i = 0; i < 8; i++) t += wloss[i];
        atomicAdd(loss, t * LOSS_SCALE);
    }
}

extern "C" void kernel_launch(void* const* d_in, const int* in_sizes, int n_in,
                              void* d_out, int out_size) {
    const float* x = (const float*)d_in[0];
    const float* cbs = (const float*)d_in[1];
    float* out = (float*)d_out;
    float* loss = out + (size_t)N_ROWS * D;
    float* codes = loss + 1;

    cudaFuncSetAttribute(k_gemm, cudaFuncAttributeMaxDynamicSharedMemorySize, SMEMT);

    k_init<<<(N_ROWS * D + 255) / 256, 256>>>(x);         // launch 0
    k_cb<<<DEPTH * K, 256>>>(cbs);                        // launch 1
    k_zero<<<1, 32>>>(loss);                              // launch 2

    for (int d = 0; d < DEPTH; d++) {
        const float* cb = cbs + (size_t)d * CB_STRIDE;
        dim3 grid(N_ROWS / BM, K / BN);
        k_gemm<<<grid, 256, SMEMT>>>(d);                  // launches 3,5,7,9
        k_finish<<<N_ROWS / 8, 256>>>(x, cb, out, codes, loss, d);
    }
}

// round 8
// speedup vs baseline: 6.9793x; 1.2992x over previous
#include <cuda_runtime.h>
#include <cuda_fp16.h>
#include <cstdint>

#define N_ROWS 8192
#define D      256
#define K      8192
#define DEPTH  4
#define CB_STRIDE ((K + 1) * D)
#define LOSS_SCALE (0.25f / (4.0f * 2097152.0f))
#define MARGIN 8e-3f
#define FLT_BIG 3.402823466e38f

#define BM 128
#define BN 128
#define NCH 4                       // 4 k-chunks of 64 halves
#define LDH 72                      // smem pitch in halves (64 + 8 pad)
#define PITCHB (LDH * 2)            // 144 bytes
#define TILEB (BM * PITCHB)         // 18432 bytes per tile
#define BOFF  TILEB
#define STAGE (2 * TILEB)           // 36864
#define NSTG  3
#define SMEMT (NSTG * STAGE)        // 110592

// ---------------- persistent scratch (aligned: vector access everywhere) ----
__device__ __align__(256) float  g_res[N_ROWS * D];
__device__ __align__(256) float  g_agg[N_ROWS * D];
__device__ __align__(256) __half g_res_h[N_ROWS * D];
__device__ __align__(256) __half g_cb_h[DEPTH * K * D];
__device__ __align__(16)  float  g_cc[DEPTH * K];
__device__ __align__(16)  unsigned long long g_top[N_ROWS * 128];  // 64 tiles x top-2

// ---------------- helpers ----------------
__device__ __forceinline__ uint32_t smem_u32(const void* p) {
    uint32_t a;
    asm("{ .reg .u64 t; cvta.to.shared.u64 t, %1; cvt.u32.u64 %0, t; }" : "=r"(a) : "l"(p));
    return a;
}
__device__ __forceinline__ uint32_t h2_as_u32(__half2 h) {
    return *reinterpret_cast<uint32_t*>(&h);
}
__device__ __forceinline__ unsigned int f2ord(float f) {
    unsigned int u = __float_as_uint(f);
    return (u & 0x80000000u) ? ~u : (u | 0x80000000u);
}
__device__ __forceinline__ float ord2f(unsigned int o) {
    unsigned int u = (o & 0x80000000u) ? (o & 0x7FFFFFFFu) : ~o;
    return __uint_as_float(u);
}
__device__ __forceinline__ void merge2(unsigned long long& b1, unsigned long long& b2,
                                       unsigned long long o1, unsigned long long o2) {
    if (o1 < b1) { b2 = (b1 < o2) ? b1 : o2; b1 = o1; }
    else if (o1 < b2) { b2 = o1; }
}
__device__ __forceinline__ void push2(unsigned long long& b1, unsigned long long& b2,
                                      unsigned long long k) {
    if (k < b1) { b2 = b1; b1 = k; }
    else if (k < b2) { b2 = k; }
}

__device__ __forceinline__ void cpa16(uint32_t dst, const void* src) {
    asm volatile("cp.async.cg.shared.global [%0], [%1], 16;" :: "r"(dst), "l"(src));
}
#define CP_COMMIT() asm volatile("cp.async.commit_group;" ::: "memory")
#define CP_WAIT(n)  asm volatile("cp.async.wait_group %0;" :: "n"(n) : "memory")

#define LDSM4(r0, r1, r2, r3, a) \
    asm volatile("ldmatrix.sync.aligned.m8n8.x4.shared.b16 {%0,%1,%2,%3}, [%4];" \
                 : "=r"(r0), "=r"(r1), "=r"(r2), "=r"(r3) : "r"(a))

#define MMA16816(c, a, b0, b1) \
    asm volatile("mma.sync.aligned.m16n8k16.row.col.f32.f16.f16.f32 " \
                 "{%0,%1,%2,%3},{%4,%5,%6,%7},{%8,%9},{%0,%1,%2,%3};" \
                 : "+f"((c)[0]), "+f"((c)[1]), "+f"((c)[2]), "+f"((c)[3]) \
                 : "r"((a)[0]), "r"((a)[1]), "r"((a)[2]), "r"((a)[3]), "r"(b0), "r"(b1))

// reduce two values across a 256-thread block; result in thread 0
__device__ __forceinline__ void blockReduce2_256(float& a, float& b) {
    __shared__ float sa[8], sb2[8];
    int lane = threadIdx.x & 31, w = threadIdx.x >> 5;
#pragma unroll
    for (int o = 16; o > 0; o >>= 1) {
        a += __shfl_down_sync(0xffffffffu, a, o);
        b += __shfl_down_sync(0xffffffffu, b, o);
    }
    if (lane == 0) { sa[w] = a; sb2[w] = b; }
    __syncthreads();
    if (w == 0) {
        a = (lane < 8) ? sa[lane] : 0.f;
        b = (lane < 8) ? sb2[lane] : 0.f;
#pragma unroll
        for (int o = 4; o > 0; o >>= 1) {
            a += __shfl_down_sync(0xffu, a, o);
            b += __shfl_down_sync(0xffu, b, o);
        }
    }
}

// ---------------- setup ----------------
__global__ void k_init(const float* __restrict__ x) {
    int i = blockIdx.x * blockDim.x + threadIdx.x;
    if (i < N_ROWS * D) {
        float v = x[i];
        g_res[i] = v; g_agg[i] = 0.f;
        g_res_h[i] = __float2half_rn(v);
    }
}

__global__ void k_cb(const float* __restrict__ cbs) {
    int rid = blockIdx.x;                     // 0 .. DEPTH*K-1
    int dd = rid / K, r = rid % K;
    float v = cbs[(size_t)dd * CB_STRIDE + (size_t)r * D + threadIdx.x];
    g_cb_h[(size_t)rid * D + threadIdx.x] = __float2half_rn(v);
    float a = v * v, b = 0.f;
    blockReduce2_256(a, b);
    if (threadIdx.x == 0) g_cc[rid] = a;
}

__global__ void k_zero(float* __restrict__ loss) {
    if (threadIdx.x == 0) *loss = 0.f;
}

// ---------------- HMMA GEMM + per-CTA top-2 ----------------
// grid = (64, 64), block = 256 (8 warps: 4 row x 2 col), 3-stage cp.async pipe
__global__ void __launch_bounds__(256, 2) k_gemm(int dep) {
    extern __shared__ char smem[];
    const uint32_t sb = smem_u32(smem);
    const int tid = threadIdx.x, lane = tid & 31, wid = tid >> 5;
    const int wm = wid & 3, wn = wid >> 2;
    const int rowBase = blockIdx.x * BM, candBase = blockIdx.y * BN;

    const char* Ag = (const char*)(g_res_h + (size_t)rowBase * D);
    const char* Bg = (const char*)(g_cb_h + ((size_t)dep * K + (size_t)candBase) * D);

    const int r0 = tid >> 3, j0 = (tid & 7);
    const uint32_t sA = r0 * PITCHB + j0 * 16;
    const uint32_t gOff = (uint32_t)r0 * 512u + (uint32_t)j0 * 16u;  // in-tile byte offset

    float acc[2][8][4];
#pragma unroll
    for (int a = 0; a < 2; a++)
#pragma unroll
        for (int b = 0; b < 8; b++)
#pragma unroll
            for (int c = 0; c < 4; c++) acc[a][b][c] = 0.f;

    const uint32_t aBase = (uint32_t)((wm * 32 + (lane & 15)) * PITCHB + ((lane >> 4) << 3) * 2);
    const uint32_t bBase = (uint32_t)((wn * 64 + (lane & 7) + ((lane >> 4) << 3)) * PITCHB +
                                      (((lane >> 3) & 1) << 3) * 2);

    // prologue: preload chunks 0 and 1 into stages 0 and 1
#pragma unroll
    for (int pc = 0; pc < 2; pc++) {
        uint32_t stg = pc * STAGE;
#pragma unroll
        for (int i = 0; i < 4; i++) {
            uint32_t so = sA + i * 32 * PITCHB;
            uint32_t go = gOff + i * 32u * 512u + (uint32_t)pc * 128u;
            cpa16(sb + stg + so, Ag + go);
            cpa16(sb + stg + BOFF + so, Bg + go);
        }
        CP_COMMIT();
    }

#pragma unroll
    for (int ch = 0; ch < NCH; ch++) {
        // wait for chunk ch; barrier doubles as write-protection for stage (ch+2)%3
        if (ch < NCH - 1) { CP_WAIT(1); } else { CP_WAIT(0); }
        __syncthreads();

        if (ch + 2 < NCH) {
            uint32_t stg = ((ch + 2) % NSTG) * STAGE;
#pragma unroll
            for (int i = 0; i < 4; i++) {
                uint32_t so = sA + i * 32 * PITCHB;
                uint32_t go = gOff + i * 32u * 512u + (uint32_t)(ch + 2) * 128u;
                cpa16(sb + stg + so, Ag + go);
                cpa16(sb + stg + BOFF + so, Bg + go);
            }
            CP_COMMIT();
        }

        const uint32_t stg = (ch % NSTG) * STAGE;
#pragma unroll
        for (int ks = 0; ks < 4; ks++) {
            uint32_t A0[4], A1[4], Bf[4][4];
            uint32_t aAddr = sb + stg + aBase + ks * 32;
            LDSM4(A0[0], A0[1], A0[2], A0[3], aAddr);
            LDSM4(A1[0], A1[1], A1[2], A1[3], aAddr + 16 * PITCHB);
            uint32_t bAddr = sb + stg + BOFF + bBase + ks * 32;
#pragma unroll
            for (int nb = 0; nb < 4; nb++)
                LDSM4(Bf[nb][0], Bf[nb][1], Bf[nb][2], Bf[nb][3], bAddr + nb * 16 * PITCHB);
#pragma unroll
            for (int nb = 0; nb < 4; nb++) {
                MMA16816(acc[0][nb * 2 + 0], A0, Bf[nb][0], Bf[nb][1]);
                MMA16816(acc[0][nb * 2 + 1], A0, Bf[nb][2], Bf[nb][3]);
                MMA16816(acc[1][nb * 2 + 0], A1, Bf[nb][0], Bf[nb][1]);
                MMA16816(acc[1][nb * 2 + 1], A1, Bf[nb][2], Bf[nb][3]);
            }
        }
    }

    // barrier before epilogue: sTop aliases stage 0, still being read by laggards
    __syncthreads();

    // ---- epilogue: per-row top-2 over this CTA's 128 cols (float compares) ----
    unsigned long long* sTop = (unsigned long long*)smem;   // [128][2][2]
    const float* cc = g_cc + (size_t)dep * K;
    const int colBase = candBase + wn * 64 + (lane & 3) * 2;

    // this thread's 16 cc values, loaded once
    float2 ccv[8];
#pragma unroll
    for (int nf = 0; nf < 8; nf++) ccv[nf] = *(const float2*)&cc[colBase + nf * 8];

#pragma unroll
    for (int mb = 0; mb < 2; mb++) {
#pragma unroll
        for (int rb = 0; rb < 2; rb++) {
            float d1 = FLT_BIG, d2 = FLT_BIG;
            int i1 = 0, i2 = 0;
#pragma unroll
            for (int nf = 0; nf < 8; nf++) {
                int col = colBase + nf * 8;
                float k0 = fmaf(-2.f, acc[mb][nf][rb * 2 + 0], ccv[nf].x);
                float k1 = fmaf(-2.f, acc[mb][nf][rb * 2 + 1], ccv[nf].y);
                if (k0 < d2) {
                    if (k0 < d1) { d2 = d1; i2 = i1; d1 = k0; i1 = col; }
                    else { d2 = k0; i2 = col; }
                }
                if (k1 < d2) {
                    if (k1 < d1) { d2 = d1; i2 = i1; d1 = k1; i1 = col + 1; }
                    else { d2 = k1; i2 = col + 1; }
                }
            }
            unsigned long long b1 =
                ((unsigned long long)f2ord(d1) << 32) | (unsigned int)i1;
            unsigned long long b2 =
                ((unsigned long long)f2ord(d2) << 32) | (unsigned int)i2;
#pragma unroll
            for (int off = 1; off <= 2; off <<= 1) {
                unsigned long long o1 = __shfl_xor_sync(0xffffffffu, b1, off);
                unsigned long long o2 = __shfl_xor_sync(0xffffffffu, b2, off);
                merge2(b1, b2, o1, o2);
            }
            if ((lane & 3) == 0) {
                int rl = wm * 32 + mb * 16 + rb * 8 + (lane >> 2);
                sTop[(rl * 2 + wn) * 2 + 0] = b1;
                sTop[(rl * 2 + wn) * 2 + 1] = b2;
            }
        }
    }
    __syncthreads();
    if (tid < 128) {
        unsigned long long p1 = sTop[(tid * 2 + 0) * 2 + 0];
        unsigned long long p2 = sTop[(tid * 2 + 0) * 2 + 1];
        merge2(p1, p2, sTop[(tid * 2 + 1) * 2 + 0], sTop[(tid * 2 + 1) * 2 + 1]);
        size_t go = (size_t)(rowBase + tid) * 128 + blockIdx.y * 2;
        g_top[go + 0] = p1;
        g_top[go + 1] = p2;
    }
}

// ---------------- fused select + rescore + update: warp per row ----------------
// grid = N_ROWS/8 = 1024, block = 256 (8 warps)
__global__ void __launch_bounds__(256) k_finish(
        const float* __restrict__ x, const float* __restrict__ cb,
        float* __restrict__ out, float* __restrict__ codes,
        float* __restrict__ loss, int dep) {
    const int w = threadIdx.x >> 5, lane = threadIdx.x & 31;
    const int row = blockIdx.x * 8 + w;
    __shared__ unsigned long long se[8][128];
    __shared__ int sql[8][128];
    __shared__ float wloss[8];

    // ---- load per-row candidate entries, warp top-2 ----
    const unsigned long long* gt = g_top + (size_t)row * 128;
    unsigned long long b1 = ~0ull, b2 = ~0ull;
#pragma unroll
    for (int i = 0; i < 4; i++) {
        unsigned long long e = gt[lane + i * 32];
        se[w][lane + i * 32] = e;
        push2(b1, b2, e);
    }
#pragma unroll
    for (int off = 16; off > 0; off >>= 1) {
        unsigned long long o1 = __shfl_xor_sync(0xffffffffu, b1, off);
        unsigned long long o2 = __shfl_xor_sync(0xffffffffu, b2, off);
        merge2(b1, b2, o1, o2);
    }
    float d1 = ord2f((unsigned int)(b1 >> 32));
    float d2 = ord2f((unsigned int)(b2 >> 32));
    int idx = (int)(b1 & 0xFFFFFFFFu);

    // residual row (registers; also reused by update)
    const float4* rr = (const float4*)(g_res + (size_t)row * D);
    float4 r0 = rr[lane * 2], r1 = rr[lane * 2 + 1];

    // ---- exact rescore when ambiguous ----
    if (d2 - d1 < MARGIN) {
        const float thr = d1 + MARGIN;
        int nq = 0;
        __syncwarp();
#pragma unroll
        for (int i = 0; i < 4; i++) {
            unsigned long long e = se[w][lane + i * 32];
            bool qf = ord2f((unsigned int)(e >> 32)) <= thr;
            unsigned m = __ballot_sync(0xffffffffu, qf);
            if (qf) {
                int pos = nq + __popc(m & ((1u << lane) - 1u));
                sql[w][pos] = (int)(e & 0xFFFFFFFFu);
            }
            nq += __popc(m);
        }
        __syncwarp();
        unsigned long long best = ~0ull;
        const float* ccd = g_cc + (size_t)dep * K;
        for (int q = 0; q < nq; q++) {
            int cand = sql[w][q];
            const float4* cr = (const float4*)(cb + (size_t)cand * D);
            float4 c0 = cr[lane * 2], c1 = cr[lane * 2 + 1];
            float p = r0.x * c0.x + r0.y * c0.y + r0.z * c0.z + r0.w * c0.w
                    + r1.x * c1.x + r1.y * c1.y + r1.z * c1.z + r1.w * c1.w;
#pragma unroll
            for (int o = 16; o > 0; o >>= 1) p += __shfl_xor_sync(0xffffffffu, p, o);
            float dist = ccd[cand] - 2.f * p;
            unsigned long long key =
                ((unsigned long long)f2ord(dist) << 32) | (unsigned int)cand;
            if (key < best) best = key;
        }
        idx = (int)(best & 0xFFFFFFFFu);
    }

    // ---- update: each lane owns 8 contiguous elements ----
    const size_t o4 = (size_t)row * (D / 4) + lane * 2;
    const float4* cbv = (const float4*)(cb + (size_t)idx * D);
    float4 q0 = cbv[lane * 2], q1 = cbv[lane * 2 + 1];
    float4 a0 = ((const float4*)g_agg)[o4], a1 = ((const float4*)g_agg)[o4 + 1];
    a0.x += q0.x; a0.y += q0.y; a0.z += q0.z; a0.w += q0.w;
    a1.x += q1.x; a1.y += q1.y; a1.z += q1.z; a1.w += q1.w;
    float4 x0 = ((const float4*)x)[o4], x1 = ((const float4*)x)[o4 + 1];

    if (dep < DEPTH - 1) {
        float4 n0, n1;
        n0.x = r0.x - q0.x; n0.y = r0.y - q0.y; n0.z = r0.z - q0.z; n0.w = r0.w - q0.w;
        n1.x = r1.x - q1.x; n1.y = r1.y - q1.y; n1.z = r1.z - q1.z; n1.w = r1.w - q1.w;
        ((float4*)g_res)[o4] = n0;
        ((float4*)g_res)[o4 + 1] = n1;
        uint4 hh;
        hh.x = h2_as_u32(__float22half2_rn(make_float2(n0.x, n0.y)));
        hh.y = h2_as_u32(__float22half2_rn(make_float2(n0.z, n0.w)));
        hh.z = h2_as_u32(__float22half2_rn(make_float2(n1.x, n1.y)));
        hh.w = h2_as_u32(__float22half2_rn(make_float2(n1.z, n1.w)));
        *(uint4*)(g_res_h + (size_t)row * D + lane * 8) = hh;
        ((float4*)g_agg)[o4] = a0;
        ((float4*)g_agg)[o4 + 1] = a1;
    } else {
        float4 ov0, ov1;
        ov0.x = x0.x + (a0.x - x0.x); ov0.y = x0.y + (a0.y - x0.y);
        ov0.z = x0.z + (a0.z - x0.z); ov0.w = x0.w + (a0.w - x0.w);
        ov1.x = x1.x + (a1.x - x1.x); ov1.y = x1.y + (a1.y - x1.y);
        ov1.z = x1.z + (a1.z - x1.z); ov1.w = x1.w + (a1.w - x1.w);
        ((float4*)out)[o4] = ov0;
        ((float4*)out)[o4 + 1] = ov1;
    }

    float d0x = x0.x - a0.x, d0y = x0.y - a0.y, d0z = x0.z - a0.z, d0w = x0.w - a0.w;
    float d1x = x1.x - a1.x, d1y = x1.y - a1.y, d1z = x1.z - a1.z, d1w = x1.w - a1.w;
    float s2 = d0x * d0x + d0y * d0y + d0z * d0z + d0w * d0w
             + d1x * d1x + d1y * d1y + d1z * d1z + d1w * d1w;
#pragma unroll
    for (int o = 16; o > 0; o >>= 1) s2 += __shfl_down_sync(0xffffffffu, s2, o);
    if (lane == 0) {
        wloss[w] = s2;
        codes[(size_t)row * DEPTH + dep] = (float)idx;
    }
    __syncthreads();
    if (threadIdx.x == 0) {
        float t = 0.f;
#pragma unroll
        for (int i = 0; i < 8; i++) t += wloss[i];
        atomicAdd(loss, t * LOSS_SCALE);
    }
}

extern "C" void kernel_launch(void* const* d_in, const int* in_sizes, int n_in,
                              void* d_out, int out_size) {
    const float* x = (const float*)d_in[0];
    const float* cbs = (const float*)d_in[1];
    float* out = (float*)d_out;
    float* loss = out + (size_t)N_ROWS * D;
    float* codes = loss + 1;

    cudaFuncSetAttribute(k_gemm, cudaFuncAttributeMaxDynamicSharedMemorySize, SMEMT);

    k_init<<<(N_ROWS * D + 255) / 256, 256>>>(x);         // launch 0
    k_cb<<<DEPTH * K, 256>>>(cbs);                        // launch 1
    k_zero<<<1, 32>>>(loss);                              // launch 2

    for (int d = 0; d < DEPTH; d++) {
        const float* cb = cbs + (size_t)d * CB_STRIDE;
        dim3 grid(N_ROWS / BM, K / BN);
        k_gemm<<<grid, 256, SMEMT>>>(d);                  // launches 3,5,7,9
        k_finish<<<N_ROWS / 8, 256>>>(x, cb, out, codes, loss, d);
    }
}

// round 9
// speedup vs baseline: 7.1428x; 1.0234x over previous
#include <cuda_runtime.h>
#include <cuda_fp16.h>
#include <cstdint>

#define N_ROWS 8192
#define D      256
#define K      8192
#define DEPTH  4
#define CB_STRIDE ((K + 1) * D)
#define LOSS_SCALE (0.25f / (4.0f * 2097152.0f))
#define MARGIN 8e-3f
#define FLT_BIG 3.402823466e38f

#define BM 128
#define LDH 72                      // smem pitch in halves (64 + 8 pad)
#define PITCHB (LDH * 2)            // 144 bytes
#define TILEB (BM * PITCHB)         // 18432 bytes per 64-half chunk tile
#define SM_B  (4 * TILEB)           // A resident: 4 chunk tiles = 73728
#define SMEMT (SM_B + 2 * TILEB)    // + 2 B stages = 110592

// ---------------- persistent scratch ----------------
__device__ __align__(256) float  g_res[N_ROWS * D];
__device__ __align__(256) float  g_agg[N_ROWS * D];
__device__ __align__(256) __half g_res_h[N_ROWS * D];
__device__ __align__(256) __half g_cb_h[DEPTH * K * D];
__device__ __align__(16)  float  g_cc[DEPTH * K];
__device__ __align__(16)  unsigned long long g_top[N_ROWS * 64];   // 32 tiles x top-2

// ---------------- helpers ----------------
__device__ __forceinline__ uint32_t smem_u32(const void* p) {
    uint32_t a;
    asm("{ .reg .u64 t; cvta.to.shared.u64 t, %1; cvt.u32.u64 %0, t; }" : "=r"(a) : "l"(p));
    return a;
}
__device__ __forceinline__ uint32_t h2_as_u32(__half2 h) {
    return *reinterpret_cast<uint32_t*>(&h);
}
__device__ __forceinline__ unsigned int f2ord(float f) {
    unsigned int u = __float_as_uint(f);
    return (u & 0x80000000u) ? ~u : (u | 0x80000000u);
}
__device__ __forceinline__ float ord2f(unsigned int o) {
    unsigned int u = (o & 0x80000000u) ? (o & 0x7FFFFFFFu) : ~o;
    return __uint_as_float(u);
}
__device__ __forceinline__ void merge2(unsigned long long& b1, unsigned long long& b2,
                                       unsigned long long o1, unsigned long long o2) {
    if (o1 < b1) { b2 = (b1 < o2) ? b1 : o2; b1 = o1; }
    else if (o1 < b2) { b2 = o1; }
}
__device__ __forceinline__ void push2(unsigned long long& b1, unsigned long long& b2,
                                      unsigned long long k) {
    if (k < b1) { b2 = b1; b1 = k; }
    else if (k < b2) { b2 = k; }
}

__device__ __forceinline__ void cpa16(uint32_t dst, const void* src) {
    asm volatile("cp.async.cg.shared.global [%0], [%1], 16;" :: "r"(dst), "l"(src));
}
#define CP_COMMIT() asm volatile("cp.async.commit_group;" ::: "memory")
#define CP_WAIT(n)  asm volatile("cp.async.wait_group %0;" :: "n"(n) : "memory")

#define LDSM4(r0, r1, r2, r3, a) \
    asm volatile("ldmatrix.sync.aligned.m8n8.x4.shared.b16 {%0,%1,%2,%3}, [%4];" \
                 : "=r"(r0), "=r"(r1), "=r"(r2), "=r"(r3) : "r"(a))

#define MMA16816(c, a, b0, b1) \
    asm volatile("mma.sync.aligned.m16n8k16.row.col.f32.f16.f16.f32 " \
                 "{%0,%1,%2,%3},{%4,%5,%6,%7},{%8,%9},{%0,%1,%2,%3};" \
                 : "+f"((c)[0]), "+f"((c)[1]), "+f"((c)[2]), "+f"((c)[3]) \
                 : "r"((a)[0]), "r"((a)[1]), "r"((a)[2]), "r"((a)[3]), "r"(b0), "r"(b1))

// reduce two values across a 256-thread block; result in thread 0
__device__ __forceinline__ void blockReduce2_256(float& a, float& b) {
    __shared__ float sa[8], sb2[8];
    int lane = threadIdx.x & 31, w = threadIdx.x >> 5;
#pragma unroll
    for (int o = 16; o > 0; o >>= 1) {
        a += __shfl_down_sync(0xffffffffu, a, o);
        b += __shfl_down_sync(0xffffffffu, b, o);
    }
    if (lane == 0) { sa[w] = a; sb2[w] = b; }
    __syncthreads();
    if (w == 0) {
        a = (lane < 8) ? sa[lane] : 0.f;
        b = (lane < 8) ? sb2[lane] : 0.f;
#pragma unroll
        for (int o = 4; o > 0; o >>= 1) {
            a += __shfl_down_sync(0xffu, a, o);
            b += __shfl_down_sync(0xffu, b, o);
        }
    }
}

// ---------------- setup ----------------
__global__ void k_init(const float* __restrict__ x) {
    int i = blockIdx.x * blockDim.x + threadIdx.x;
    if (i < N_ROWS * D) {
        float v = x[i];
        g_res[i] = v; g_agg[i] = 0.f;
        g_res_h[i] = __float2half_rn(v);
    }
}

__global__ void k_cb(const float* __restrict__ cbs) {
    int rid = blockIdx.x;                     // 0 .. DEPTH*K-1
    int dd = rid / K, r = rid % K;
    float v = cbs[(size_t)dd * CB_STRIDE + (size_t)r * D + threadIdx.x];
    g_cb_h[(size_t)rid * D + threadIdx.x] = __float2half_rn(v);
    float a = v * v, b = 0.f;
    blockReduce2_256(a, b);
    if (threadIdx.x == 0) g_cc[rid] = a;
}

__global__ void k_zero(float* __restrict__ loss) {
    if (threadIdx.x == 0) *loss = 0.f;
}

// consume one 128-col sub-tile's accumulators into running float top-2
__device__ __forceinline__ void consume_acc(
        float acc[2][8][4], const float* __restrict__ cc, int colBase,
        float d1[4], float d2[4], int i1[4], int i2[4]) {
#pragma unroll
    for (int mb = 0; mb < 2; mb++) {
#pragma unroll
        for (int rb = 0; rb < 2; rb++) {
            const int s = mb * 2 + rb;
#pragma unroll
            for (int nf = 0; nf < 8; nf++) {
                int col = colBase + nf * 8;
                float2 c2 = *(const float2*)&cc[col];
                float k0 = fmaf(-2.f, acc[mb][nf][rb * 2 + 0], c2.x);
                float k1 = fmaf(-2.f, acc[mb][nf][rb * 2 + 1], c2.y);
                if (k0 < d2[s]) {
                    if (k0 < d1[s]) { d2[s] = d1[s]; i2[s] = i1[s]; d1[s] = k0; i1[s] = col; }
                    else { d2[s] = k0; i2[s] = col; }
                }
                if (k1 < d2[s]) {
                    if (k1 < d1[s]) { d2[s] = d1[s]; i2[s] = i1[s]; d1[s] = k1; i1[s] = col + 1; }
                    else { d2[s] = k1; i2[s] = col + 1; }
                }
                acc[mb][nf][rb * 2 + 0] = 0.f;
                acc[mb][nf][rb * 2 + 1] = 0.f;
            }
        }
    }
}

// ---------------- HMMA GEMM + per-CTA top-2 ----------------
// grid = (64, 32), block = 256 (8 warps: 4 row x 2 col)
// A (128x256) resident in smem; B streamed in 2 stages, 8 chunk-iterations.
__global__ void __launch_bounds__(256, 2) k_gemm(int dep) {
    extern __shared__ char smem[];
    const uint32_t sb = smem_u32(smem);
    const int tid = threadIdx.x, lane = tid & 31, wid = tid >> 5;
    const int wm = wid & 3, wn = wid >> 2;
    const int rowBase = blockIdx.x * BM, candBase = blockIdx.y * 256;

    const char* Ag = (const char*)(g_res_h + (size_t)rowBase * D);
    const char* Bg = (const char*)(g_cb_h + ((size_t)dep * K + (size_t)candBase) * D);

    const int r0 = tid >> 3, j0 = (tid & 7);
    const uint32_t sA = r0 * PITCHB + j0 * 16;
    const uint32_t gOff = (uint32_t)r0 * 512u + (uint32_t)j0 * 16u;

    float acc[2][8][4];
#pragma unroll
    for (int a = 0; a < 2; a++)
#pragma unroll
        for (int b = 0; b < 8; b++)
#pragma unroll
            for (int c = 0; c < 4; c++) acc[a][b][c] = 0.f;

    float d1[4] = {FLT_BIG, FLT_BIG, FLT_BIG, FLT_BIG};
    float d2[4] = {FLT_BIG, FLT_BIG, FLT_BIG, FLT_BIG};
    int   i1[4] = {0, 0, 0, 0}, i2[4] = {0, 0, 0, 0};

    const uint32_t aBase = (uint32_t)((wm * 32 + (lane & 15)) * PITCHB + ((lane >> 4) << 3) * 2);
    const uint32_t bBase = (uint32_t)((wn * 64 + (lane & 7) + ((lane >> 4) << 3)) * PITCHB +
                                      (((lane >> 3) & 1) << 3) * 2);
    const float* cc = g_cc + (size_t)dep * K;
    const int thColBase = candBase + wn * 64 + (lane & 3) * 2;

    // prologue: all of A (4 chunk tiles) + B chunk 0 into stage 0, one group
#pragma unroll
    for (int chA = 0; chA < 4; chA++) {
#pragma unroll
        for (int i = 0; i < 4; i++) {
            uint32_t so = sA + i * 32 * PITCHB;
            cpa16(sb + chA * TILEB + so, Ag + gOff + i * 32u * 512u + chA * 128u);
        }
    }
#pragma unroll
    for (int i = 0; i < 4; i++) {
        uint32_t so = sA + i * 32 * PITCHB;
        cpa16(sb + SM_B + so, Bg + gOff + i * 32u * 512u);
    }
    CP_COMMIT();

#pragma unroll
    for (int it = 0; it < 8; it++) {
        CP_WAIT(0);
        __syncthreads();

        if (it < 7) {
            const int itn = it + 1;
            const uint32_t bsrc = (uint32_t)(itn >> 2) * 65536u + (uint32_t)(itn & 3) * 128u;
            const uint32_t bstg = SM_B + (uint32_t)(itn & 1) * TILEB;
#pragma unroll
            for (int i = 0; i < 4; i++) {
                uint32_t so = sA + i * 32 * PITCHB;
                cpa16(sb + bstg + so, Bg + gOff + i * 32u * 512u + bsrc);
            }
            CP_COMMIT();
        }

        const uint32_t aTile = sb + (uint32_t)(it & 3) * TILEB;
        const uint32_t bTile = sb + SM_B + (uint32_t)(it & 1) * TILEB;
#pragma unroll
        for (int ks = 0; ks < 4; ks++) {
            uint32_t A0[4], A1[4], Bf[4][4];
            uint32_t aAddr = aTile + aBase + ks * 32;
            LDSM4(A0[0], A0[1], A0[2], A0[3], aAddr);
            LDSM4(A1[0], A1[1], A1[2], A1[3], aAddr + 16 * PITCHB);
            uint32_t bAddr = bTile + bBase + ks * 32;
#pragma unroll
            for (int nb = 0; nb < 4; nb++)
                LDSM4(Bf[nb][0], Bf[nb][1], Bf[nb][2], Bf[nb][3], bAddr + nb * 16 * PITCHB);
#pragma unroll
            for (int nb = 0; nb < 4; nb++) {
                MMA16816(acc[0][nb * 2 + 0], A0, Bf[nb][0], Bf[nb][1]);
                MMA16816(acc[0][nb * 2 + 1], A0, Bf[nb][2], Bf[nb][3]);
                MMA16816(acc[1][nb * 2 + 0], A1, Bf[nb][0], Bf[nb][1]);
                MMA16816(acc[1][nb * 2 + 1], A1, Bf[nb][2], Bf[nb][3]);
            }
        }

        if ((it & 3) == 3)   // finished a 128-col sub-tile (ct = it>>2)
            consume_acc(acc, cc, thColBase + (it >> 2) * 128, d1, d2, i1, i2);
    }

    // final pack + merge + store (sTop aliases A chunk-0 tile; safe: all reads done)
    __syncthreads();
    unsigned long long* sTop = (unsigned long long*)smem;   // [128][2][2]
#pragma unroll
    for (int s = 0; s < 4; s++) {
        unsigned long long b1 =
            ((unsigned long long)f2ord(d1[s]) << 32) | (unsigned int)i1[s];
        unsigned long long b2 =
            ((unsigned long long)f2ord(d2[s]) << 32) | (unsigned int)i2[s];
#pragma unroll
        for (int off = 1; off <= 2; off <<= 1) {
            unsigned long long o1 = __shfl_xor_sync(0xffffffffu, b1, off);
            unsigned long long o2 = __shfl_xor_sync(0xffffffffu, b2, off);
            merge2(b1, b2, o1, o2);
        }
        if ((lane & 3) == 0) {
            int rl = wm * 32 + (s >> 1) * 16 + (s & 1) * 8 + (lane >> 2);
            sTop[(rl * 2 + wn) * 2 + 0] = b1;
            sTop[(rl * 2 + wn) * 2 + 1] = b2;
        }
    }
    __syncthreads();
    if (tid < 128) {
        unsigned long long p1 = sTop[(tid * 2 + 0) * 2 + 0];
        unsigned long long p2 = sTop[(tid * 2 + 0) * 2 + 1];
        merge2(p1, p2, sTop[(tid * 2 + 1) * 2 + 0], sTop[(tid * 2 + 1) * 2 + 1]);
        size_t go = (size_t)(rowBase + tid) * 64 + blockIdx.y * 2;
        g_top[go + 0] = p1;
        g_top[go + 1] = p2;
    }
}

// ---------------- fused select + rescore + update: warp per row ----------------
// grid = N_ROWS/8 = 1024, block = 256 (8 warps)
__global__ void __launch_bounds__(256) k_finish(
        const float* __restrict__ x, const float* __restrict__ cb,
        float* __restrict__ out, float* __restrict__ codes,
        float* __restrict__ loss, int dep) {
    const int w = threadIdx.x >> 5, lane = threadIdx.x & 31;
    const int row = blockIdx.x * 8 + w;
    __shared__ unsigned long long se[8][64];
    __shared__ int sql[8][64];
    __shared__ float wloss[8];

    // ---- load per-row candidate entries, warp top-2 ----
    const unsigned long long* gt = g_top + (size_t)row * 64;
    unsigned long long b1 = ~0ull, b2 = ~0ull;
#pragma unroll
    for (int i = 0; i < 2; i++) {
        unsigned long long e = gt[lane + i * 32];
        se[w][lane + i * 32] = e;
        push2(b1, b2, e);
    }
#pragma unroll
    for (int off = 16; off > 0; off >>= 1) {
        unsigned long long o1 = __shfl_xor_sync(0xffffffffu, b1, off);
        unsigned long long o2 = __shfl_xor_sync(0xffffffffu, b2, off);
        merge2(b1, b2, o1, o2);
    }
    float d1 = ord2f((unsigned int)(b1 >> 32));
    float d2 = ord2f((unsigned int)(b2 >> 32));
    int idx = (int)(b1 & 0xFFFFFFFFu);

    // residual row
    const float4* rr = (const float4*)(g_res + (size_t)row * D);
    float4 r0 = rr[lane * 2], r1 = rr[lane * 2 + 1];

    // ---- exact rescore when ambiguous ----
    if (d2 - d1 < MARGIN) {
        const float thr = d1 + MARGIN;
        int nq = 0;
        __syncwarp();
#pragma unroll
        for (int i = 0; i < 2; i++) {
            unsigned long long e = se[w][lane + i * 32];
            bool qf = ord2f((unsigned int)(e >> 32)) <= thr;
            unsigned m = __ballot_sync(0xffffffffu, qf);
            if (qf) {
                int pos = nq + __popc(m & ((1u << lane) - 1u));
                sql[w][pos] = (int)(e & 0xFFFFFFFFu);
            }
            nq += __popc(m);
        }
        __syncwarp();
        unsigned long long best = ~0ull;
        const float* ccd = g_cc + (size_t)dep * K;
        for (int q = 0; q < nq; q++) {
            int cand = sql[w][q];
            const float4* cr = (const float4*)(cb + (size_t)cand * D);
            float4 c0 = cr[lane * 2], c1 = cr[lane * 2 + 1];
            float p = r0.x * c0.x + r0.y * c0.y + r0.z * c0.z + r0.w * c0.w
                    + r1.x * c1.x + r1.y * c1.y + r1.z * c1.z + r1.w * c1.w;
#pragma unroll
            for (int o = 16; o > 0; o >>= 1) p += __shfl_xor_sync(0xffffffffu, p, o);
            float dist = ccd[cand] - 2.f * p;
            unsigned long long key =
                ((unsigned long long)f2ord(dist) << 32) | (unsigned int)cand;
            if (key < best) best = key;
        }
        idx = (int)(best & 0xFFFFFFFFu);
    }

    // ---- update: each lane owns 8 contiguous elements ----
    const size_t o4 = (size_t)row * (D / 4) + lane * 2;
    const float4* cbv = (const float4*)(cb + (size_t)idx * D);
    float4 q0 = cbv[lane * 2], q1 = cbv[lane * 2 + 1];
    float4 a0 = ((const float4*)g_agg)[o4], a1 = ((const float4*)g_agg)[o4 + 1];
    a0.x += q0.x; a0.y += q0.y; a0.z += q0.z; a0.w += q0.w;
    a1.x += q1.x; a1.y += q1.y; a1.z += q1.z; a1.w += q1.w;
    float4 x0 = ((const float4*)x)[o4], x1 = ((const float4*)x)[o4 + 1];

    if (dep < DEPTH - 1) {
        float4 n0, n1;
        n0.x = r0.x - q0.x; n0.y = r0.y - q0.y; n0.z = r0.z - q0.z; n0.w = r0.w - q0.w;
        n1.x = r1.x - q1.x; n1.y = r1.y - q1.y; n1.z = r1.z - q1.z; n1.w = r1.w - q1.w;
        ((float4*)g_res)[o4] = n0;
        ((float4*)g_res)[o4 + 1] = n1;
        uint4 hh;
        hh.x = h2_as_u32(__float22half2_rn(make_float2(n0.x, n0.y)));
        hh.y = h2_as_u32(__float22half2_rn(make_float2(n0.z, n0.w)));
        hh.z = h2_as_u32(__float22half2_rn(make_float2(n1.x, n1.y)));
        hh.w = h2_as_u32(__float22half2_rn(make_float2(n1.z, n1.w)));
        *(uint4*)(g_res_h + (size_t)row * D + lane * 8) = hh;
        ((float4*)g_agg)[o4] = a0;
        ((float4*)g_agg)[o4 + 1] = a1;
    } else {
        float4 ov0, ov1;
        ov0.x = x0.x + (a0.x - x0.x); ov0.y = x0.y + (a0.y - x0.y);
        ov0.z = x0.z + (a0.z - x0.z); ov0.w = x0.w + (a0.w - x0.w);
        ov1.x = x1.x + (a1.x - x1.x); ov1.y = x1.y + (a1.y - x1.y);
        ov1.z = x1.z + (a1.z - x1.z); ov1.w = x1.w + (a1.w - x1.w);
        ((float4*)out)[o4] = ov0;
        ((float4*)out)[o4 + 1] = ov1;
    }

    float d0x = x0.x - a0.x, d0y = x0.y - a0.y, d0z = x0.z - a0.z, d0w = x0.w - a0.w;
    float d1x = x1.x - a1.x, d1y = x1.y - a1.y, d1z = x1.z - a1.z, d1w = x1.w - a1.w;
    float s2 = d0x * d0x + d0y * d0y + d0z * d0z + d0w * d0w
             + d1x * d1x + d1y * d1y + d1z * d1z + d1w * d1w;
#pragma unroll
    for (int o = 16; o > 0; o >>= 1) s2 += __shfl_down_sync(0xffffffffu, s2, o);
    if (lane == 0) {
        wloss[w] = s2;
        codes[(size_t)row * DEPTH + dep] = (float)idx;
    }
    __syncthreads();
    if (threadIdx.x == 0) {
        float t = 0.f;
#pragma unroll
        for (int i = 0; i < 8; i++) t += wloss[i];
        atomicAdd(loss, t * LOSS_SCALE);
    }
}

extern "C" void kernel_launch(void* const* d_in, const int* in_sizes, int n_in,
                              void* d_out, int out_size) {
    const float* x = (const float*)d_in[0];
    const float* cbs = (const float*)d_in[1];
    float* out = (float*)d_out;
    float* loss = out + (size_t)N_ROWS * D;
    float* codes = loss + 1;

    cudaFuncSetAttribute(k_gemm, cudaFuncAttributeMaxDynamicSharedMemorySize, SMEMT);

    k_init<<<(N_ROWS * D + 255) / 256, 256>>>(x);         // launch 0
    k_cb<<<DEPTH * K, 256>>>(cbs);                        // launch 1
    k_zero<<<1, 32>>>(loss);                              // launch 2

    for (int d = 0; d < DEPTH; d++) {
        const float* cb = cbs + (size_t)d * CB_STRIDE;
        dim3 grid(N_ROWS / BM, K / 256);
        k_gemm<<<grid, 256, SMEMT>>>(d);                  // launches 3,5,7,9
        k_finish<<<N_ROWS / 8, 256>>>(x, cb, out, codes, loss, d);
    }
}

// round 10
// speedup vs baseline: 7.2242x; 1.0114x over previous
#include <cuda_runtime.h>
#include <cuda_fp16.h>
#include <cstdint>

#define N_ROWS 8192
#define D      256
#define K      8192
#define DEPTH  4
#define CB_STRIDE ((K + 1) * D)
#define LOSS_SCALE (0.25f / (4.0f * 2097152.0f))
#define MARGIN 8e-3f
#define FLT_BIG 3.402823466e38f

#define BM 128
#define TILE16 16384                 // 128 rows x 128B, pad-free (XOR swizzle)
#define SM_B  (4 * TILE16)           // A resident: 4 chunk tiles = 65536
#define NBSTG 3
#define SMEMT (SM_B + NBSTG * TILE16)   // 114688 (2 CTAs/SM -> 224KB)

// ---------------- persistent scratch ----------------
__device__ __align__(256) float  g_res[N_ROWS * D];
__device__ __align__(256) float  g_agg[N_ROWS * D];
__device__ __align__(256) __half g_res_h[N_ROWS * D];
__device__ __align__(256) __half g_cb_h[DEPTH * K * D];
__device__ __align__(16)  float  g_cc[DEPTH * K];
__device__ __align__(16)  unsigned long long g_top[N_ROWS * 64];   // 32 tiles x top-2

// ---------------- helpers ----------------
__device__ __forceinline__ uint32_t smem_u32(const void* p) {
    uint32_t a;
    asm("{ .reg .u64 t; cvta.to.shared.u64 t, %1; cvt.u32.u64 %0, t; }" : "=r"(a) : "l"(p));
    return a;
}
__device__ __forceinline__ uint32_t swz(uint32_t x) { return x ^ ((x >> 3) & 0x70u); }
__device__ __forceinline__ uint32_t h2_as_u32(__half2 h) {
    return *reinterpret_cast<uint32_t*>(&h);
}
__device__ __forceinline__ unsigned int f2ord(float f) {
    unsigned int u = __float_as_uint(f);
    return (u & 0x80000000u) ? ~u : (u | 0x80000000u);
}
__device__ __forceinline__ float ord2f(unsigned int o) {
    unsigned int u = (o & 0x80000000u) ? (o & 0x7FFFFFFFu) : ~o;
    return __uint_as_float(u);
}
__device__ __forceinline__ void merge2(unsigned long long& b1, unsigned long long& b2,
                                       unsigned long long o1, unsigned long long o2) {
    if (o1 < b1) { b2 = (b1 < o2) ? b1 : o2; b1 = o1; }
    else if (o1 < b2) { b2 = o1; }
}
__device__ __forceinline__ void push2(unsigned long long& b1, unsigned long long& b2,
                                      unsigned long long k) {
    if (k < b1) { b2 = b1; b1 = k; }
    else if (k < b2) { b2 = k; }
}

__device__ __forceinline__ void cpa16(uint32_t dst, const void* src) {
    asm volatile("cp.async.cg.shared.global [%0], [%1], 16;" :: "r"(dst), "l"(src));
}
#define CP_COMMIT() asm volatile("cp.async.commit_group;" ::: "memory")
#define CP_WAIT(n)  asm volatile("cp.async.wait_group %0;" :: "n"(n) : "memory")

#define LDSM4(r0, r1, r2, r3, a) \
    asm volatile("ldmatrix.sync.aligned.m8n8.x4.shared.b16 {%0,%1,%2,%3}, [%4];" \
                 : "=r"(r0), "=r"(r1), "=r"(r2), "=r"(r3) : "r"(a))

#define MMA16816(c, a, b0, b1) \
    asm volatile("mma.sync.aligned.m16n8k16.row.col.f32.f16.f16.f32 " \
                 "{%0,%1,%2,%3},{%4,%5,%6,%7},{%8,%9},{%0,%1,%2,%3};" \
                 : "+f"((c)[0]), "+f"((c)[1]), "+f"((c)[2]), "+f"((c)[3]) \
                 : "r"((a)[0]), "r"((a)[1]), "r"((a)[2]), "r"((a)[3]), "r"(b0), "r"(b1))

// reduce two values across a 256-thread block; result in thread 0
__device__ __forceinline__ void blockReduce2_256(float& a, float& b) {
    __shared__ float sa[8], sb2[8];
    int lane = threadIdx.x & 31, w = threadIdx.x >> 5;
#pragma unroll
    for (int o = 16; o > 0; o >>= 1) {
        a += __shfl_down_sync(0xffffffffu, a, o);
        b += __shfl_down_sync(0xffffffffu, b, o);
    }
    if (lane == 0) { sa[w] = a; sb2[w] = b; }
    __syncthreads();
    if (w == 0) {
        a = (lane < 8) ? sa[lane] : 0.f;
        b = (lane < 8) ? sb2[lane] : 0.f;
#pragma unroll
        for (int o = 4; o > 0; o >>= 1) {
            a += __shfl_down_sync(0xffu, a, o);
            b += __shfl_down_sync(0xffu, b, o);
        }
    }
}

// ---------------- setup ----------------
__global__ void k_init(const float* __restrict__ x) {
    int i = blockIdx.x * blockDim.x + threadIdx.x;
    if (i < N_ROWS * D) {
        float v = x[i];
        g_res[i] = v; g_agg[i] = 0.f;
        g_res_h[i] = __float2half_rn(v);
    }
}

__global__ void k_cb(const float* __restrict__ cbs) {
    int rid = blockIdx.x;                     // 0 .. DEPTH*K-1
    int dd = rid / K, r = rid % K;
    float v = cbs[(size_t)dd * CB_STRIDE + (size_t)r * D + threadIdx.x];
    g_cb_h[(size_t)rid * D + threadIdx.x] = __float2half_rn(v);
    float a = v * v, b = 0.f;
    blockReduce2_256(a, b);
    if (threadIdx.x == 0) g_cc[rid] = a;
}

__global__ void k_zero(float* __restrict__ loss) {
    if (threadIdx.x == 0) *loss = 0.f;
}

// consume one 128-col sub-tile's accumulators into running float top-2
__device__ __forceinline__ void consume_acc(
        float acc[2][8][4], const float* __restrict__ cc, int colBase,
        float d1[4], float d2[4], int i1[4], int i2[4]) {
#pragma unroll
    for (int mb = 0; mb < 2; mb++) {
#pragma unroll
        for (int rb = 0; rb < 2; rb++) {
            const int s = mb * 2 + rb;
#pragma unroll
            for (int nf = 0; nf < 8; nf++) {
                int col = colBase + nf * 8;
                float2 c2 = *(const float2*)&cc[col];
                float k0 = fmaf(-2.f, acc[mb][nf][rb * 2 + 0], c2.x);
                float k1 = fmaf(-2.f, acc[mb][nf][rb * 2 + 1], c2.y);
                if (k0 < d2[s]) {
                    if (k0 < d1[s]) { d2[s] = d1[s]; i2[s] = i1[s]; d1[s] = k0; i1[s] = col; }
                    else { d2[s] = k0; i2[s] = col; }
                }
                if (k1 < d2[s]) {
                    if (k1 < d1[s]) { d2[s] = d1[s]; i2[s] = i1[s]; d1[s] = k1; i1[s] = col + 1; }
                    else { d2[s] = k1; i2[s] = col + 1; }
                }
                acc[mb][nf][rb * 2 + 0] = 0.f;
                acc[mb][nf][rb * 2 + 1] = 0.f;
            }
        }
    }
}

// ---------------- HMMA GEMM + per-CTA top-2 ----------------
// grid = (64, 32), block = 256 (8 warps: 4 row x 2 col)
// A (128x256) resident (XOR-swizzled, pad-free); B streamed through 3 stages,
// prefetch distance 2 (CP_WAIT(1)) so each B tile has ~2 compute iterations
// of latency cover.
__global__ void __launch_bounds__(256, 2) k_gemm(int dep) {
    extern __shared__ char smem[];
    const uint32_t sb = smem_u32(smem);
    const int tid = threadIdx.x, lane = tid & 31, wid = tid >> 5;
    const int wm = wid & 3, wn = wid >> 2;
    const int rowBase = blockIdx.x * BM, candBase = blockIdx.y * 256;

    const char* Ag = (const char*)(g_res_h + (size_t)rowBase * D);
    const char* Bg = (const char*)(g_cb_h + ((size_t)dep * K + (size_t)candBase) * D);

    const int r0 = tid >> 3, j0 = (tid & 7);
    const uint32_t gOff = (uint32_t)r0 * 512u + (uint32_t)j0 * 16u;  // src offset
    // swizzled in-tile dst offsets for the 4 row-groups this thread stores
    uint32_t sdst[4];
#pragma unroll
    for (int i = 0; i < 4; i++) sdst[i] = swz((uint32_t)(r0 + i * 32) * 128u + j0 * 16u);

    float acc[2][8][4];
#pragma unroll
    for (int a = 0; a < 2; a++)
#pragma unroll
        for (int b = 0; b < 8; b++)
#pragma unroll
            for (int c = 0; c < 4; c++) acc[a][b][c] = 0.f;

    float d1[4] = {FLT_BIG, FLT_BIG, FLT_BIG, FLT_BIG};
    float d2[4] = {FLT_BIG, FLT_BIG, FLT_BIG, FLT_BIG};
    int   i1[4] = {0, 0, 0, 0}, i2[4] = {0, 0, 0, 0};

    // linear (pre-swizzle) ldmatrix offsets
    const uint32_t aLin0 = (uint32_t)((wm * 32 + (lane & 15)) * 128 + (lane >> 4) * 16);
    const uint32_t aLin1 = aLin0 + 16 * 128;
    const uint32_t bLin  = (uint32_t)((wn * 64 + (lane & 7) + ((lane >> 4) << 3)) * 128 +
                                      ((lane >> 3) & 1) * 16);
    const float* cc = g_cc + (size_t)dep * K;
    const int thColBase = candBase + wn * 64 + (lane & 3) * 2;

    // prologue: group0 = all of A (4 chunk tiles) + B(0); group1 = B(1)
#pragma unroll
    for (int chA = 0; chA < 4; chA++)
#pragma unroll
        for (int i = 0; i < 4; i++)
            cpa16(sb + chA * TILE16 + sdst[i],
                  Ag + gOff + i * 32u * 512u + chA * 128u);
#pragma unroll
    for (int i = 0; i < 4; i++)
        cpa16(sb + SM_B + sdst[i], Bg + gOff + i * 32u * 512u);
    CP_COMMIT();
#pragma unroll
    for (int i = 0; i < 4; i++)
        cpa16(sb + SM_B + TILE16 + sdst[i], Bg + gOff + i * 32u * 512u + 128u);
    CP_COMMIT();

#pragma unroll
    for (int it = 0; it < 8; it++) {
        if (it < 7) { CP_WAIT(1); } else { CP_WAIT(0); }
        __syncthreads();

        if (it + 2 < 8) {
            const int itn = it + 2;
            const uint32_t bsrc = (uint32_t)(itn >> 2) * 65536u + (uint32_t)(itn & 3) * 128u;
            const uint32_t bstg = SM_B + (uint32_t)(itn % NBSTG) * TILE16;
#pragma unroll
            for (int i = 0; i < 4; i++)
                cpa16(sb + bstg + sdst[i], Bg + gOff + i * 32u * 512u + bsrc);
            CP_COMMIT();
        }

        const uint32_t aTile = sb + (uint32_t)(it & 3) * TILE16;
        const uint32_t bTile = sb + SM_B + (uint32_t)(it % NBSTG) * TILE16;
#pragma unroll
        for (int ks = 0; ks < 4; ks++) {
            uint32_t A0[4], A1[4], Bf[4][4];
            LDSM4(A0[0], A0[1], A0[2], A0[3], aTile + swz(aLin0 + ks * 32));
            LDSM4(A1[0], A1[1], A1[2], A1[3], aTile + swz(aLin1 + ks * 32));
#pragma unroll
            for (int nb = 0; nb < 4; nb++)
                LDSM4(Bf[nb][0], Bf[nb][1], Bf[nb][2], Bf[nb][3],
                      bTile + swz(bLin + nb * 16 * 128 + ks * 32));
#pragma unroll
            for (int nb = 0; nb < 4; nb++) {
                MMA16816(acc[0][nb * 2 + 0], A0, Bf[nb][0], Bf[nb][1]);
                MMA16816(acc[0][nb * 2 + 1], A0, Bf[nb][2], Bf[nb][3]);
                MMA16816(acc[1][nb * 2 + 0], A1, Bf[nb][0], Bf[nb][1]);
                MMA16816(acc[1][nb * 2 + 1], A1, Bf[nb][2], Bf[nb][3]);
            }
        }

        if ((it & 3) == 3)   // finished a 128-col sub-tile (ct = it>>2)
            consume_acc(acc, cc, thColBase + (it >> 2) * 128, d1, d2, i1, i2);
    }

    // final pack + merge + store (sTop aliases A tile 0; all reads done)
    __syncthreads();
    unsigned long long* sTop = (unsigned long long*)smem;   // [128][2][2]
#pragma unroll
    for (int s = 0; s < 4; s++) {
        unsigned long long b1 =
            ((unsigned long long)f2ord(d1[s]) << 32) | (unsigned int)i1[s];
        unsigned long long b2 =
            ((unsigned long long)f2ord(d2[s]) << 32) | (unsigned int)i2[s];
#pragma unroll
        for (int off = 1; off <= 2; off <<= 1) {
            unsigned long long o1 = __shfl_xor_sync(0xffffffffu, b1, off);
            unsigned long long o2 = __shfl_xor_sync(0xffffffffu, b2, off);
            merge2(b1, b2, o1, o2);
        }
        if ((lane & 3) == 0) {
            int rl = wm * 32 + (s >> 1) * 16 + (s & 1) * 8 + (lane >> 2);
            sTop[(rl * 2 + wn) * 2 + 0] = b1;
            sTop[(rl * 2 + wn) * 2 + 1] = b2;
        }
    }
    __syncthreads();
    if (tid < 128) {
        unsigned long long p1 = sTop[(tid * 2 + 0) * 2 + 0];
        unsigned long long p2 = sTop[(tid * 2 + 0) * 2 + 1];
        merge2(p1, p2, sTop[(tid * 2 + 1) * 2 + 0], sTop[(tid * 2 + 1) * 2 + 1]);
        size_t go = (size_t)(rowBase + tid) * 64 + blockIdx.y * 2;
        g_top[go + 0] = p1;
        g_top[go + 1] = p2;
    }
}

// ---------------- fused select + rescore + update: warp per row ----------------
// grid = N_ROWS/8 = 1024, block = 256 (8 warps)
__global__ void __launch_bounds__(256) k_finish(
        const float* __restrict__ x, const float* __restrict__ cb,
        float* __restrict__ out, float* __restrict__ codes,
        float* __restrict__ loss, int dep) {
    const int w = threadIdx.x >> 5, lane = threadIdx.x & 31;
    const int row = blockIdx.x * 8 + w;
    __shared__ unsigned long long se[8][64];
    __shared__ int sql[8][64];
    __shared__ float wloss[8];

    // ---- load per-row candidate entries, warp top-2 ----
    const unsigned long long* gt = g_top + (size_t)row * 64;
    unsigned long long b1 = ~0ull, b2 = ~0ull;
#pragma unroll
    for (int i = 0; i < 2; i++) {
        unsigned long long e = gt[lane + i * 32];
        se[w][lane + i * 32] = e;
        push2(b1, b2, e);
    }
#pragma unroll
    for (int off = 16; off > 0; off >>= 1) {
        unsigned long long o1 = __shfl_xor_sync(0xffffffffu, b1, off);
        unsigned long long o2 = __shfl_xor_sync(0xffffffffu, b2, off);
        merge2(b1, b2, o1, o2);
    }
    float d1 = ord2f((unsigned int)(b1 >> 32));
    float d2 = ord2f((unsigned int)(b2 >> 32));
    int idx = (int)(b1 & 0xFFFFFFFFu);

    // residual row
    const float4* rr = (const float4*)(g_res + (size_t)row * D);
    float4 r0 = rr[lane * 2], r1 = rr[lane * 2 + 1];

    // ---- exact rescore when ambiguous ----
    if (d2 - d1 < MARGIN) {
        const float thr = d1 + MARGIN;
        int nq = 0;
        __syncwarp();
#pragma unroll
        for (int i = 0; i < 2; i++) {
            unsigned long long e = se[w][lane + i * 32];
            bool qf = ord2f((unsigned int)(e >> 32)) <= thr;
            unsigned m = __ballot_sync(0xffffffffu, qf);
            if (qf) {
                int pos = nq + __popc(m & ((1u << lane) - 1u));
                sql[w][pos] = (int)(e & 0xFFFFFFFFu);
            }
            nq += __popc(m);
        }
        __syncwarp();
        unsigned long long best = ~0ull;
        const float* ccd = g_cc + (size_t)dep * K;
        for (int q = 0; q < nq; q++) {
            int cand = sql[w][q];
            const float4* cr = (const float4*)(cb + (size_t)cand * D);
            float4 c0 = cr[lane * 2], c1 = cr[lane * 2 + 1];
            float p = r0.x * c0.x + r0.y * c0.y + r0.z * c0.z + r0.w * c0.w
                    + r1.x * c1.x + r1.y * c1.y + r1.z * c1.z + r1.w * c1.w;
#pragma unroll
            for (int o = 16; o > 0; o >>= 1) p += __shfl_xor_sync(0xffffffffu, p, o);
            float dist = ccd[cand] - 2.f * p;
            unsigned long long key =
                ((unsigned long long)f2ord(dist) << 32) | (unsigned int)cand;
            if (key < best) best = key;
        }
        idx = (int)(best & 0xFFFFFFFFu);
    }

    // ---- update: each lane owns 8 contiguous elements ----
    const size_t o4 = (size_t)row * (D / 4) + lane * 2;
    const float4* cbv = (const float4*)(cb + (size_t)idx * D);
    float4 q0 = cbv[lane * 2], q1 = cbv[lane * 2 + 1];
    float4 a0 = ((const float4*)g_agg)[o4], a1 = ((const float4*)g_agg)[o4 + 1];
    a0.x += q0.x; a0.y += q0.y; a0.z += q0.z; a0.w += q0.w;
    a1.x += q1.x; a1.y += q1.y; a1.z += q1.z; a1.w += q1.w;
    float4 x0 = ((const float4*)x)[o4], x1 = ((const float4*)x)[o4 + 1];

    if (dep < DEPTH - 1) {
        float4 n0, n1;
        n0.x = r0.x - q0.x; n0.y = r0.y - q0.y; n0.z = r0.z - q0.z; n0.w = r0.w - q0.w;
        n1.x = r1.x - q1.x; n1.y = r1.y - q1.y; n1.z = r1.z - q1.z; n1.w = r1.w - q1.w;
        ((float4*)g_res)[o4] = n0;
        ((float4*)g_res)[o4 + 1] = n1;
        uint4 hh;
        hh.x = h2_as_u32(__float22half2_rn(make_float2(n0.x, n0.y)));
        hh.y = h2_as_u32(__float22half2_rn(make_float2(n0.z, n0.w)));
        hh.z = h2_as_u32(__float22half2_rn(make_float2(n1.x, n1.y)));
        hh.w = h2_as_u32(__float22half2_rn(make_float2(n1.z, n1.w)));
        *(uint4*)(g_res_h + (size_t)row * D + lane * 8) = hh;
        ((float4*)g_agg)[o4] = a0;
        ((float4*)g_agg)[o4 + 1] = a1;
    } else {
        float4 ov0, ov1;
        ov0.x = x0.x + (a0.x - x0.x); ov0.y = x0.y + (a0.y - x0.y);
        ov0.z = x0.z + (a0.z - x0.z); ov0.w = x0.w + (a0.w - x0.w);
        ov1.x = x1.x + (a1.x - x1.x); ov1.y = x1.y + (a1.y - x1.y);
        ov1.z = x1.z + (a1.z - x1.z); ov1.w = x1.w + (a1.w - x1.w);
        ((float4*)out)[o4] = ov0;
        ((float4*)out)[o4 + 1] = ov1;
    }

    float d0x = x0.x - a0.x, d0y = x0.y - a0.y, d0z = x0.z - a0.z, d0w = x0.w - a0.w;
    float d1x = x1.x - a1.x, d1y = x1.y - a1.y, d1z = x1.z - a1.z, d1w = x1.w - a1.w;
    float s2 = d0x * d0x + d0y * d0y + d0z * d0z + d0w * d0w
             + d1x * d1x + d1y * d1y + d1z * d1z + d1w * d1w;
#pragma unroll
    for (int o = 16; o > 0; o >>= 1) s2 += __shfl_down_sync(0xffffffffu, s2, o);
    if (lane == 0) {
        wloss[w] = s2;
        codes[(size_t)row * DEPTH + dep] = (float)idx;
    }
    __syncthreads();
    if (threadIdx.x == 0) {
        float t = 0.f;
#pragma unroll
        for (int i = 0; i < 8; i++) t += wloss[i];
        atomicAdd(loss, t * LOSS_SCALE);
    }
}

extern "C" void kernel_launch(void* const* d_in, const int* in_sizes, int n_in,
                              void* d_out, int out_size) {
    const float* x = (const float*)d_in[0];
    const float* cbs = (const float*)d_in[1];
    float* out = (float*)d_out;
    float* loss = out + (size_t)N_ROWS * D;
    float* codes = loss + 1;

    cudaFuncSetAttribute(k_gemm, cudaFuncAttributeMaxDynamicSharedMemorySize, SMEMT);

    k_init<<<(N_ROWS * D + 255) / 256, 256>>>(x);         // launch 0
    k_cb<<<DEPTH * K, 256>>>(cbs);                        // launch 1
    k_zero<<<1, 32>>>(loss);                              // launch 2

    for (int d = 0; d < DEPTH; d++) {
        const float* cb = cbs + (size_t)d * CB_STRIDE;
        dim3 grid(N_ROWS / BM, K / 256);
        k_gemm<<<grid, 256, SMEMT>>>(d);                  // launches 3,5,7,9
        k_finish<<<N_ROWS / 8, 256>>>(x, cb, out, codes, loss, d);
    }
}